// round 1
// baseline (speedup 1.0000x reference)
#include <cuda_runtime.h>
#include <math.h>

#define T 1024
#define H 1024
#define E 64
#define ISZ 512
#define TWO_I 1024
#define KTOP 6
#define NGRP 8
#define TKG 3
#define CAP 256
#define A_TOT (T*KTOP)
#define NSH_HALF 1024
#define NSH_2 2048

// ---------------- scratch (static device globals; no allocations) ----------------
__device__ float g_logits[T*E];
__device__ int   g_eidx[A_TOT];
__device__ float g_w[A_TOT];
__device__ int   g_cnt[E];
__device__ int   g_off[E+1];
__device__ int   g_slot[A_TOT];
__device__ int   g_perm[A_TOT];
__device__ int   g_rowpos[A_TOT];
__device__ float g_guS[T*NSH_2];          // shared-expert gate_up output [T,2048]
__device__ float g_actS[T*NSH_HALF];      // shared-expert activation     [T,1024]
__device__ float g_gu[A_TOT*TWO_I];       // routed gate_up output        [A,1024]
__device__ float g_act[A_TOT*ISZ];        // routed activation            [A,512]
__device__ float g_y[A_TOT*H];            // routed expert output rows    [A,1024]

// ---------------- generic tiled SGEMM: C[M,N] = A[M,K] @ B[K,N] ----------------
// 64x64 tile, BK=16, 256 threads, 4x4 microtile. Assumes M%64==0, N%64==0, K%16==0.
__global__ __launch_bounds__(256) void sgemm64(
    const float* __restrict__ A, const float* __restrict__ B, float* __restrict__ C,
    int Kd, int N)
{
    __shared__ float As[16][68];
    __shared__ float Bs[16][68];
    int tid = threadIdx.x;
    int tx = tid & 15, ty = tid >> 4;
    int rowBase = blockIdx.y * 64, colBase = blockIdx.x * 64;
    int ar = tid >> 2, ac = (tid & 3) * 4;   // A loader: 4 thr/row, 64 rows
    int br = tid >> 4, bc = tx * 4;          // B loader: 16 rows x 16 thr

    const float* Arow = A + (size_t)(rowBase + ar) * Kd + ac;
    const float* Bptr = B + (size_t)br * N + colBase + bc;

    float acc[4][4] = {};
    for (int kb = 0; kb < Kd; kb += 16) {
        float4 av = *(const float4*)(Arow + kb);
        As[ac+0][ar]=av.x; As[ac+1][ar]=av.y; As[ac+2][ar]=av.z; As[ac+3][ar]=av.w;
        float4 bv = *(const float4*)(Bptr + (size_t)kb * N);
        *(float4*)&Bs[br][bc] = bv;
        __syncthreads();
#pragma unroll
        for (int kk = 0; kk < 16; kk++) {
            float4 a = *(const float4*)&As[kk][ty*4];
            float4 b = *(const float4*)&Bs[kk][tx*4];
            acc[0][0]+=a.x*b.x; acc[0][1]+=a.x*b.y; acc[0][2]+=a.x*b.z; acc[0][3]+=a.x*b.w;
            acc[1][0]+=a.y*b.x; acc[1][1]+=a.y*b.y; acc[1][2]+=a.y*b.z; acc[1][3]+=a.y*b.w;
            acc[2][0]+=a.z*b.x; acc[2][1]+=a.z*b.y; acc[2][2]+=a.z*b.z; acc[2][3]+=a.z*b.w;
            acc[3][0]+=a.w*b.x; acc[3][1]+=a.w*b.y; acc[3][2]+=a.w*b.z; acc[3][3]+=a.w*b.w;
        }
        __syncthreads();
    }
#pragma unroll
    for (int i = 0; i < 4; i++) {
        float4 o = make_float4(acc[i][0], acc[i][1], acc[i][2], acc[i][3]);
        *(float4*)&C[(size_t)(rowBase + ty*4 + i) * N + colBase + tx*4] = o;
    }
}

// ---------------- grouped SGEMM over experts (with optional row gather) ----------------
// blockIdx.z = expert; rows are the expert's compacted global rows [off[e], off[e]+cnt).
// gather=1: A row = Asrc + (perm[gr]/KTOP)*Kd (token gather from hidden_states)
// gather=0: A row = Asrc + gr*Kd
__global__ __launch_bounds__(256) void grouped_sgemm(
    const float* __restrict__ Asrc, const float* __restrict__ Bbase, float* __restrict__ Cbase,
    int Kd, int N, long long Bstride, int gather)
{
    int e = blockIdx.z;
    int cnt = g_cnt[e]; if (cnt > CAP) cnt = CAP;
    int m0 = blockIdx.y * 64;
    if (m0 >= cnt) return;
    int off = g_off[e];
    const float* B = Bbase + (size_t)e * (size_t)Bstride;

    __shared__ float As[16][68];
    __shared__ float Bs[16][68];
    int tid = threadIdx.x;
    int tx = tid & 15, ty = tid >> 4;
    int colBase = blockIdx.x * 64;
    int ar = tid >> 2, ac = (tid & 3) * 4;
    int br = tid >> 4, bc = tx * 4;

    int lm = m0 + ar;
    bool aok = lm < cnt;
    const float* Arow = Asrc;
    if (aok) {
        int gr = off + lm;
        size_t rowi = gather ? (size_t)(g_perm[gr] / KTOP) : (size_t)gr;
        Arow = Asrc + rowi * Kd + ac;
    }
    const float* Bptr = B + (size_t)br * N + colBase + bc;

    float acc[4][4] = {};
    for (int kb = 0; kb < Kd; kb += 16) {
        float4 av = aok ? *(const float4*)(Arow + kb) : make_float4(0.f,0.f,0.f,0.f);
        As[ac+0][ar]=av.x; As[ac+1][ar]=av.y; As[ac+2][ar]=av.z; As[ac+3][ar]=av.w;
        float4 bv = *(const float4*)(Bptr + (size_t)kb * N);
        *(float4*)&Bs[br][bc] = bv;
        __syncthreads();
#pragma unroll
        for (int kk = 0; kk < 16; kk++) {
            float4 a = *(const float4*)&As[kk][ty*4];
            float4 b = *(const float4*)&Bs[kk][tx*4];
            acc[0][0]+=a.x*b.x; acc[0][1]+=a.x*b.y; acc[0][2]+=a.x*b.z; acc[0][3]+=a.x*b.w;
            acc[1][0]+=a.y*b.x; acc[1][1]+=a.y*b.y; acc[1][2]+=a.y*b.z; acc[1][3]+=a.y*b.w;
            acc[2][0]+=a.z*b.x; acc[2][1]+=a.z*b.y; acc[2][2]+=a.z*b.z; acc[2][3]+=a.z*b.w;
            acc[3][0]+=a.w*b.x; acc[3][1]+=a.w*b.y; acc[3][2]+=a.w*b.z; acc[3][3]+=a.w*b.w;
        }
        __syncthreads();
    }
#pragma unroll
    for (int i = 0; i < 4; i++) {
        int m = m0 + ty*4 + i;
        if (m < cnt) {
            size_t gr = (size_t)(off + m);
            float4 o = make_float4(acc[i][0], acc[i][1], acc[i][2], acc[i][3]);
            *(float4*)&Cbase[gr * N + colBase + tx*4] = o;
        }
    }
}

// ---------------- silu(g)*u over [rows, 2*half] -> [rows, half] ----------------
__global__ void silu_mul_k(const float* __restrict__ gu, float* __restrict__ act,
                           int rows, int half)
{
    int i = blockIdx.x * blockDim.x + threadIdx.x;
    if (i >= rows * half) return;
    int r = i / half, j = i - r * half;
    float g = gu[(size_t)r * 2 * half + j];
    float u = gu[(size_t)r * 2 * half + half + j];
    act[i] = (g / (1.f + expf(-g))) * u;
}

// ---------------- grouped top-k router (one thread per token) ----------------
__global__ void topk_k(const float* __restrict__ bias)
{
    int t = blockIdx.x * blockDim.x + threadIdx.x;
    if (t >= T) return;
    float sc[E], sb[E];
#pragma unroll
    for (int e = 0; e < E; e++) {
        float l = g_logits[t*E + e];
        float s = 1.f / (1.f + expf(-l));
        sc[e] = s; sb[e] = s + bias[e];
    }
    float gs[NGRP];
#pragma unroll
    for (int g = 0; g < NGRP; g++) {
        float m1 = -1e30f, m2 = -1e30f;
#pragma unroll
        for (int j = 0; j < 8; j++) {
            float v = sb[g*8 + j];
            if (v > m1) { m2 = m1; m1 = v; } else if (v > m2) { m2 = v; }
        }
        gs[g] = m1 + m2;
    }
    unsigned gsel = 0;
#pragma unroll
    for (int it = 0; it < TKG; it++) {
        float best = -1e30f; int bi = 0;
        for (int g = 0; g < NGRP; g++)
            if (!((gsel >> g) & 1) && gs[g] > best) { best = gs[g]; bi = g; }
        gsel |= 1u << bi;
    }
    unsigned long long used = 0; float wsum = 0.f;
    float wk[KTOP];
#pragma unroll
    for (int it = 0; it < KTOP; it++) {
        float best = -1e30f; int bi = 0;
        for (int e = 0; e < E; e++) {
            if (((gsel >> (e >> 3)) & 1) && !((used >> e) & 1) && sb[e] > best) {
                best = sb[e]; bi = e;
            }
        }
        used |= 1ull << bi;
        g_eidx[t*KTOP + it] = bi;
        wk[it] = sc[bi]; wsum += sc[bi];
    }
    float inv = 1.f / wsum;
#pragma unroll
    for (int k = 0; k < KTOP; k++) g_w[t*KTOP + k] = wk[k] * inv;
}

// ---------------- dispatch ----------------
__global__ void zero_cnt_k() { int i = threadIdx.x; if (i < E) g_cnt[i] = 0; }

__global__ void slots_k() {
    int a = blockIdx.x * blockDim.x + threadIdx.x;
    if (a < A_TOT) { int e = g_eidx[a]; g_slot[a] = atomicAdd(&g_cnt[e], 1); }
}

__global__ void scan_k() {
    if (threadIdx.x == 0) {
        int s = 0;
        for (int e = 0; e < E; e++) { g_off[e] = s; s += g_cnt[e]; }
        g_off[E] = s;
    }
}

__global__ void fill_k() {
    int a = blockIdx.x * blockDim.x + threadIdx.x;
    if (a < A_TOT) {
        int e = g_eidx[a], s = g_slot[a];
        if (s < CAP) { int r = g_off[e] + s; g_perm[r] = a; g_rowpos[a] = r; }
        else g_rowpos[a] = -1;
    }
}

// ---------------- combine: out = shared + SCALE * sum_k w_k * y_k ----------------
__global__ __launch_bounds__(256) void combine_k(float* __restrict__ out)
{
    int t = blockIdx.x;
    int h0 = threadIdx.x * 4;
    float4 acc = *(float4*)&out[(size_t)t*H + h0];
#pragma unroll
    for (int k = 0; k < KTOP; k++) {
        int a = t*KTOP + k;
        int r = g_rowpos[a];
        if (r >= 0) {
            float w = 2.5f * g_w[a];
            float4 y = *(const float4*)&g_y[(size_t)r*H + h0];
            acc.x += w*y.x; acc.y += w*y.y; acc.z += w*y.z; acc.w += w*y.w;
        }
    }
    *(float4*)&out[(size_t)t*H + h0] = acc;
}

// ---------------- launch ----------------
extern "C" void kernel_launch(void* const* d_in, const int* in_sizes, int n_in,
                              void* d_out, int out_size)
{
    const float* x        = (const float*)d_in[0];  // [T,H]
    const float* gate_w   = (const float*)d_in[1];  // [H,E]
    const float* e_bias   = (const float*)d_in[2];  // [E]
    const float* w_gu     = (const float*)d_in[3];  // [E,H,2I]
    const float* w_dn     = (const float*)d_in[4];  // [E,I,H]
    const float* ws_gu    = (const float*)d_in[5];  // [H,2048]
    const float* ws_dn    = (const float*)d_in[6];  // [1024,H]
    float* out = (float*)d_out;

    float *p_guS, *p_actS, *p_logits, *p_gu, *p_act, *p_y;
    cudaGetSymbolAddress((void**)&p_guS,    g_guS);
    cudaGetSymbolAddress((void**)&p_actS,   g_actS);
    cudaGetSymbolAddress((void**)&p_logits, g_logits);
    cudaGetSymbolAddress((void**)&p_gu,     g_gu);
    cudaGetSymbolAddress((void**)&p_act,    g_act);
    cudaGetSymbolAddress((void**)&p_y,      g_y);

    // shared experts MLP -> d_out
    sgemm64<<<dim3(NSH_2/64, T/64), 256>>>(x, ws_gu, p_guS, H, NSH_2);
    silu_mul_k<<<(T*NSH_HALF + 255)/256, 256>>>(p_guS, p_actS, T, NSH_HALF);
    sgemm64<<<dim3(H/64, T/64), 256>>>(p_actS, ws_dn, out, NSH_HALF, H);

    // router
    sgemm64<<<dim3(1, T/64), 256>>>(x, gate_w, p_logits, H, E);
    topk_k<<<(T + 255)/256, 256>>>(e_bias);

    // dispatch
    zero_cnt_k<<<1, 64>>>();
    slots_k<<<(A_TOT + 255)/256, 256>>>();
    scan_k<<<1, 32>>>();
    fill_k<<<(A_TOT + 255)/256, 256>>>();

    // routed experts: gate_up (gathered), silu*mul, down
    grouped_sgemm<<<dim3(TWO_I/64, CAP/64, E), 256>>>(
        x, w_gu, p_gu, H, TWO_I, (long long)H * TWO_I, 1);
    silu_mul_k<<<(A_TOT*ISZ + 255)/256, 256>>>(p_gu, p_act, A_TOT, ISZ);
    grouped_sgemm<<<dim3(H/64, CAP/64, E), 256>>>(
        p_act, w_dn, p_y, ISZ, H, (long long)ISZ * H, 0);

    // combine
    combine_k<<<T, 256>>>(out);
}

// round 4
// speedup vs baseline: 1.4161x; 1.4161x over previous
#include <cuda_runtime.h>
#include <cuda_bf16.h>
#include <cstdint>
#include <math.h>

#define T 1024
#define H 1024
#define E 64
#define ISZ 512
#define TWO_I 1024
#define KTOP 6
#define NGRP 8
#define TKG 3
#define CAP 256
#define A_TOT (T*KTOP)
#define NSH_HALF 1024
#define NSH_2 2048

// GEMM tiling
#define BM 128
#define BN 128
#define BKT 32
#define APITCH 36
#define BPITCH 136
#define A_STAGE (BM*APITCH)          // floats
#define B_STAGE (BKT*BPITCH)         // floats
#define SMEM_FLOATS (2*A_STAGE + 2*B_STAGE)
#define SMEM_BYTES (SMEM_FLOATS*4 + 128*8)

// ---------------- scratch ----------------
__device__ float g_w[A_TOT];
__device__ int   g_eidx[A_TOT];
__device__ int   g_cnt[E];
__device__ int   g_off[E+1];
__device__ int   g_slot[A_TOT];
__device__ int   g_perm[A_TOT];
__device__ int   g_rowpos[A_TOT];
__device__ float g_guS[T*NSH_2];
__device__ float g_actS[T*NSH_HALF];
__device__ float g_gu[A_TOT*TWO_I];
__device__ float g_act[A_TOT*ISZ];
__device__ float g_y[A_TOT*H];

// ---------------- PTX helpers ----------------
__device__ __forceinline__ uint32_t smem_u32(const void* p){
    uint32_t a;
    asm("{ .reg .u64 t; cvta.to.shared.u64 t, %1; cvt.u32.u64 %0, t; }" : "=r"(a) : "l"(p));
    return a;
}
#define CP16(d,s) asm volatile("cp.async.cg.shared.global [%0], [%1], 16;" :: "r"(d), "l"(s))
#define CP_COMMIT() asm volatile("cp.async.commit_group;" ::: "memory")
#define CP_WAIT1()  asm volatile("cp.async.wait_group 1;" ::: "memory")
#define CP_WAIT0()  asm volatile("cp.async.wait_group 0;" ::: "memory")

__device__ __forceinline__ void mma_bf16(float* c, const uint32_t* a, const uint32_t* b){
    asm volatile(
        "mma.sync.aligned.m16n8k16.row.col.f32.bf16.bf16.f32 "
        "{%0,%1,%2,%3}, {%4,%5,%6,%7}, {%8,%9}, {%0,%1,%2,%3};"
        : "+f"(c[0]), "+f"(c[1]), "+f"(c[2]), "+f"(c[3])
        : "r"(a[0]), "r"(a[1]), "r"(a[2]), "r"(a[3]), "r"(b[0]), "r"(b[1]));
}

// split two fp32 into packed bf16x2 hi/lo (elementwise x = hi + lo + O(2^-18 x))
__device__ __forceinline__ void split_pair(float x0, float x1, uint32_t& h, uint32_t& l){
    __nv_bfloat162 hv = __floats2bfloat162_rn(x0, x1);
    float f0 = __bfloat162float(__low2bfloat16(hv));
    float f1 = __bfloat162float(__high2bfloat16(hv));
    __nv_bfloat162 lv = __floats2bfloat162_rn(x0 - f0, x1 - f1);
    h = *reinterpret_cast<uint32_t*>(&hv);
    l = *reinterpret_cast<uint32_t*>(&lv);
}

// ---------------- bf16x3 mma.sync GEMM ----------------
// C[M,N] = A[M,K] @ B[K,N] ; B row-major [K,Nfull] (+ per-expert stride).
// mode 0: dense rows. mode 1: grouped, rows gathered via g_perm (token=perm/KTOP).
// mode 2: grouped, rows = compacted off[e]+m.
__global__ void __launch_bounds__(256) mma_gemm(
    const float* __restrict__ A, const float* __restrict__ B, float* __restrict__ C,
    int Kd, int Nfull, long long BexpStride, int mode)
{
    extern __shared__ __align__(16) float smem[];
    float* As = smem;                       // [2][BM*APITCH]
    float* Bs = smem + 2*A_STAGE;           // [2][BKT*BPITCH]
    const float** rowptr = (const float**)(smem + SMEM_FLOATS);

    int tid = threadIdx.x, wid = tid >> 5, lane = tid & 31;
    int n0 = blockIdx.x * BN, m0 = blockIdx.y * BM;
    int cnt = 1 << 30, off = 0;
    const float* Bm = B;
    if (mode){
        int e = blockIdx.z;
        cnt = g_cnt[e]; if (cnt > CAP) cnt = CAP;
        if (m0 >= cnt) return;
        off = g_off[e];
        Bm = B + (size_t)e * (size_t)BexpStride;
    }
    if (tid < BM){
        int m = m0 + tid;
        const float* src;
        if (mode == 0)      src = A + (size_t)m * Kd;
        else if (m >= cnt)  src = A;
        else if (mode == 1) src = A + (size_t)(g_perm[off + m] / KTOP) * Kd;
        else                src = A + (size_t)(off + m) * Kd;
        rowptr[tid] = src;
    }
    __syncthreads();

    // loader roles
    int arow = tid >> 1, ahalf = (tid & 1) * 16;   // 2 thr/row, 16 floats each
    int brow = tid >> 3, bch  = tid & 7;           // 8 thr/row, 4x16B chunks

    const int NK = Kd / BKT;

    auto load_stage = [&](int s, int kt){
        int kc = kt * BKT;
        {
            const float* src = rowptr[arow] + kc + ahalf;
            uint32_t d = smem_u32(As + s*A_STAGE + arow*APITCH + ahalf);
            CP16(d,      src);
            CP16(d + 16, src + 4);
            CP16(d + 32, src + 8);
            CP16(d + 48, src + 12);
        }
        {
            const float* src = Bm + (size_t)(kc + brow) * Nfull + n0;
            uint32_t d = smem_u32(Bs + s*B_STAGE + brow*BPITCH);
            #pragma unroll
            for (int j = 0; j < 4; j++){
                int f = (bch + 8*j) * 4;
                CP16(d + f*4, src + f);
            }
        }
    };

    float acc[4][4][4];
    #pragma unroll
    for (int i = 0; i < 4; i++)
        #pragma unroll
        for (int j = 0; j < 4; j++)
            #pragma unroll
            for (int v = 0; v < 4; v++) acc[i][j][v] = 0.f;

    int wm = (wid >> 2) * 64, wn = (wid & 3) * 32;
    int lg = lane >> 2, lt = lane & 3;

    load_stage(0, 0);
    CP_COMMIT();

    for (int kt = 0; kt < NK; kt++){
        int s = kt & 1;
        if (kt + 1 < NK){
            load_stage(s ^ 1, kt + 1);
            CP_COMMIT();
            CP_WAIT1();
        } else {
            CP_WAIT0();
        }
        __syncthreads();

        const float* as = As + s*A_STAGE;
        const float* bs = Bs + s*B_STAGE;
        #pragma unroll
        for (int ks = 0; ks < 2; ks++){               // two k16 steps per BKT=32
            int kk = ks * 16;
            uint32_t ah[4][4], al[4][4], bh[4][2], bl[4][2];
            #pragma unroll
            for (int mt = 0; mt < 4; mt++){
                const float* ap = as + (wm + mt*16 + lg) * APITCH + kk + 2*lt;
                split_pair(ap[0],            ap[1],              ah[mt][0], al[mt][0]);
                split_pair(ap[8*APITCH],     ap[8*APITCH + 1],   ah[mt][1], al[mt][1]);
                split_pair(ap[8],            ap[9],              ah[mt][2], al[mt][2]);
                split_pair(ap[8*APITCH + 8], ap[8*APITCH + 9],   ah[mt][3], al[mt][3]);
            }
            #pragma unroll
            for (int nt = 0; nt < 4; nt++){
                const float* bp = bs + (kk + 2*lt) * BPITCH + wn + nt*8 + lg;
                split_pair(bp[0],          bp[BPITCH],   bh[nt][0], bl[nt][0]);
                split_pair(bp[8*BPITCH],   bp[9*BPITCH], bh[nt][1], bl[nt][1]);
            }
            #pragma unroll
            for (int mt = 0; mt < 4; mt++)
                #pragma unroll
                for (int nt = 0; nt < 4; nt++){
                    mma_bf16(acc[mt][nt], ah[mt], bh[nt]);
                    mma_bf16(acc[mt][nt], ah[mt], bl[nt]);
                    mma_bf16(acc[mt][nt], al[mt], bh[nt]);
                }
        }
        __syncthreads();
    }

    // epilogue
    #pragma unroll
    for (int mt = 0; mt < 4; mt++){
        int r0 = m0 + wm + mt*16 + lg;
        int r1 = r0 + 8;
        bool v0 = (mode == 0) || (r0 < cnt);
        bool v1 = (mode == 0) || (r1 < cnt);
        size_t cr0 = (size_t)((mode == 0) ? r0 : off + r0) * Nfull;
        size_t cr1 = (size_t)((mode == 0) ? r1 : off + r1) * Nfull;
        #pragma unroll
        for (int nt = 0; nt < 4; nt++){
            int col = n0 + wn + nt*8 + 2*lt;
            if (v0) *(float2*)(C + cr0 + col) = make_float2(acc[mt][nt][0], acc[mt][nt][1]);
            if (v1) *(float2*)(C + cr1 + col) = make_float2(acc[mt][nt][2], acc[mt][nt][3]);
        }
    }
}

// ---------------- fused router + grouped top-k (one block per token) ----------------
__global__ __launch_bounds__(256) void router_topk(
    const float* __restrict__ x, const float* __restrict__ gw, const float* __restrict__ bias)
{
    __shared__ float xs[H];
    __shared__ float part[4][64];
    __shared__ float sc[64], sbb[64];
    int t = blockIdx.x;
    ((float4*)xs)[threadIdx.x] = ((const float4*)(x + (size_t)t * H))[threadIdx.x];
    __syncthreads();
    int c = threadIdx.x >> 6, e = threadIdx.x & 63;
    const float* w = gw + (size_t)c * 256 * 64 + e;
    float acc = 0.f;
    #pragma unroll 8
    for (int h = 0; h < 256; h++) acc += xs[c * 256 + h] * w[(size_t)h * 64];
    part[c][e] = acc;
    __syncthreads();
    if (threadIdx.x < 64){
        float l = part[0][e] + part[1][e] + part[2][e] + part[3][e];
        float s = 1.f / (1.f + expf(-l));
        sc[e] = s; sbb[e] = s + bias[e];
    }
    __syncthreads();
    if (threadIdx.x == 0){
        float gs[NGRP];
        #pragma unroll
        for (int g = 0; g < NGRP; g++){
            float m1 = -1e30f, m2 = -1e30f;
            #pragma unroll
            for (int j = 0; j < 8; j++){
                float v = sbb[g * 8 + j];
                if (v > m1){ m2 = m1; m1 = v; } else if (v > m2){ m2 = v; }
            }
            gs[g] = m1 + m2;
        }
        unsigned gsel = 0;
        #pragma unroll
        for (int it = 0; it < TKG; it++){
            float best = -1e30f; int bi = 0;
            for (int g = 0; g < NGRP; g++)
                if (!((gsel >> g) & 1) && gs[g] > best){ best = gs[g]; bi = g; }
            gsel |= 1u << bi;
        }
        unsigned long long used = 0; float wsum = 0.f;
        float wk[KTOP]; int ek[KTOP];
        #pragma unroll
        for (int it = 0; it < KTOP; it++){
            float best = -1e30f; int bi = 0;
            for (int ee = 0; ee < 64; ee++){
                if (((gsel >> (ee >> 3)) & 1) && !((used >> ee) & 1) && sbb[ee] > best){
                    best = sbb[ee]; bi = ee;
                }
            }
            used |= 1ull << bi;
            ek[it] = bi; wk[it] = sc[bi]; wsum += sc[bi];
        }
        float inv = 1.f / wsum;
        #pragma unroll
        for (int k = 0; k < KTOP; k++){
            g_eidx[t * KTOP + k] = ek[k];
            g_w[t * KTOP + k] = wk[k] * inv;
        }
    }
}

// ---------------- silu(g)*u ----------------
__global__ void silu_mul_k(const float* __restrict__ gu, float* __restrict__ act,
                           int rows, int half)
{
    int i = blockIdx.x * blockDim.x + threadIdx.x;
    if (i >= rows * half) return;
    int r = i / half, j = i - r * half;
    float g = gu[(size_t)r * 2 * half + j];
    float u = gu[(size_t)r * 2 * half + half + j];
    act[i] = (g / (1.f + expf(-g))) * u;
}

// ---------------- dispatch ----------------
__global__ void zero_cnt_k(){ int i = threadIdx.x; if (i < E) g_cnt[i] = 0; }

__global__ void slots_k(){
    int a = blockIdx.x * blockDim.x + threadIdx.x;
    if (a < A_TOT){ int e = g_eidx[a]; g_slot[a] = atomicAdd(&g_cnt[e], 1); }
}

__global__ void scan_k(){
    if (threadIdx.x == 0){
        int s = 0;
        for (int e = 0; e < E; e++){ g_off[e] = s; s += g_cnt[e] > CAP ? CAP : g_cnt[e]; }
        g_off[E] = s;
    }
}

__global__ void fill_k(){
    int a = blockIdx.x * blockDim.x + threadIdx.x;
    if (a < A_TOT){
        int e = g_eidx[a], s = g_slot[a];
        if (s < CAP){ int r = g_off[e] + s; g_perm[r] = a; g_rowpos[a] = r; }
        else g_rowpos[a] = -1;
    }
}

// ---------------- combine ----------------
__global__ __launch_bounds__(256) void combine_k(float* __restrict__ out)
{
    int t = blockIdx.x;
    int h0 = threadIdx.x * 4;
    float4 acc = *(float4*)&out[(size_t)t * H + h0];
    #pragma unroll
    for (int k = 0; k < KTOP; k++){
        int a = t * KTOP + k;
        int r = g_rowpos[a];
        if (r >= 0){
            float w = 2.5f * g_w[a];
            float4 y = *(const float4*)&g_y[(size_t)r * H + h0];
            acc.x += w * y.x; acc.y += w * y.y; acc.z += w * y.z; acc.w += w * y.w;
        }
    }
    *(float4*)&out[(size_t)t * H + h0] = acc;
}

// ---------------- launch ----------------
extern "C" void kernel_launch(void* const* d_in, const int* in_sizes, int n_in,
                              void* d_out, int out_size)
{
    const float* x      = (const float*)d_in[0];  // [T,H]
    const float* gate_w = (const float*)d_in[1];  // [H,E]
    const float* e_bias = (const float*)d_in[2];  // [E]
    const float* w_gu   = (const float*)d_in[3];  // [E,H,2I]
    const float* w_dn   = (const float*)d_in[4];  // [E,I,H]
    const float* ws_gu  = (const float*)d_in[5];  // [H,2048]
    const float* ws_dn  = (const float*)d_in[6];  // [1024,H]
    float* out = (float*)d_out;

    float *p_guS, *p_actS, *p_gu, *p_act, *p_y;
    cudaGetSymbolAddress((void**)&p_guS,  g_guS);
    cudaGetSymbolAddress((void**)&p_actS, g_actS);
    cudaGetSymbolAddress((void**)&p_gu,   g_gu);
    cudaGetSymbolAddress((void**)&p_act,  g_act);
    cudaGetSymbolAddress((void**)&p_y,    g_y);

    cudaFuncSetAttribute(mma_gemm, cudaFuncAttributeMaxDynamicSharedMemorySize, SMEM_BYTES);

    // router + dispatch
    router_topk<<<T, 256>>>(x, gate_w, e_bias);
    zero_cnt_k<<<1, 64>>>();
    slots_k<<<(A_TOT + 255) / 256, 256>>>();
    scan_k<<<1, 32>>>();
    fill_k<<<(A_TOT + 255) / 256, 256>>>();

    // shared experts MLP -> out
    mma_gemm<<<dim3(NSH_2 / BN, T / BM, 1), 256, SMEM_BYTES>>>(
        x, ws_gu, p_guS, H, NSH_2, 0, 0);
    silu_mul_k<<<(T * NSH_HALF + 255) / 256, 256>>>(p_guS, p_actS, T, NSH_HALF);
    mma_gemm<<<dim3(H / BN, T / BM, 1), 256, SMEM_BYTES>>>(
        p_actS, ws_dn, out, NSH_HALF, H, 0, 0);

    // routed experts
    mma_gemm<<<dim3(TWO_I / BN, CAP / BM, E), 256, SMEM_BYTES>>>(
        x, w_gu, p_gu, H, TWO_I, (long long)H * TWO_I, 1);
    silu_mul_k<<<(A_TOT * ISZ + 255) / 256, 256>>>(p_gu, p_act, A_TOT, ISZ);
    mma_gemm<<<dim3(H / BN, CAP / BM, E), 256, SMEM_BYTES>>>(
        p_act, w_dn, p_y, ISZ, H, (long long)ISZ * H, 2);

    // combine
    combine_k<<<T, 256>>>(out);
}

// round 7
// speedup vs baseline: 1.8987x; 1.3408x over previous
#include <cuda_runtime.h>
#include <cuda_bf16.h>
#include <cstdint>
#include <math.h>

#define T 1024
#define H 1024
#define E 64
#define ISZ 512
#define TWO_I 1024
#define KTOP 6
#define NGRP 8
#define TKG 3
#define CAP 256
#define A_TOT (T*KTOP)
#define NSH_HALF 1024
#define NSH_2 2048

// GEMM tiling
#define BN 128
#define BKT 32
#define APITCH 36
#define BPITCH 136
#define B_STAGE (BKT*BPITCH)         // floats

// ---------------- scratch ----------------
__device__ float g_w[A_TOT];
__device__ int   g_eidx[A_TOT];
__device__ int   g_cnt[E];
__device__ int   g_off[E+1];
__device__ int   g_slot[A_TOT];
__device__ int   g_perm[A_TOT];
__device__ int   g_rowpos[A_TOT];
__device__ float g_guS[T*NSH_2];
__device__ float g_actS[T*NSH_HALF];
__device__ float g_gu[A_TOT*TWO_I];
__device__ float g_act[A_TOT*ISZ];
__device__ float g_y[A_TOT*H];

// ---------------- PTX helpers ----------------
__device__ __forceinline__ uint32_t smem_u32(const void* p){
    uint32_t a;
    asm("{ .reg .u64 t; cvta.to.shared.u64 t, %1; cvt.u32.u64 %0, t; }" : "=r"(a) : "l"(p));
    return a;
}
#define CP16(d,s) asm volatile("cp.async.cg.shared.global [%0], [%1], 16;" :: "r"(d), "l"(s))
#define CP_COMMIT() asm volatile("cp.async.commit_group;" ::: "memory")
#define CP_WAIT1()  asm volatile("cp.async.wait_group 1;" ::: "memory")
#define CP_WAIT0()  asm volatile("cp.async.wait_group 0;" ::: "memory")

__device__ __forceinline__ void mma_bf16(float* c, const uint32_t* a, const uint32_t* b){
    asm volatile(
        "mma.sync.aligned.m16n8k16.row.col.f32.bf16.bf16.f32 "
        "{%0,%1,%2,%3}, {%4,%5,%6,%7}, {%8,%9}, {%0,%1,%2,%3};"
        : "+f"(c[0]), "+f"(c[1]), "+f"(c[2]), "+f"(c[3])
        : "r"(a[0]), "r"(a[1]), "r"(a[2]), "r"(a[3]), "r"(b[0]), "r"(b[1]));
}

// exact split: hi = truncate-to-bf16(x) via bit mask (x = hi + lo_exact),
// lo = round-to-bf16(x - hi). Packed pairs.
__device__ __forceinline__ void split_pair(float x0, float x1, uint32_t& h, uint32_t& l){
    uint32_t u0 = __float_as_uint(x0), u1 = __float_as_uint(x1);
    h = __byte_perm(u0, u1, 0x7632);
    float f0 = __uint_as_float(u0 & 0xFFFF0000u);
    float f1 = __uint_as_float(u1 & 0xFFFF0000u);
    __nv_bfloat162 lv = __floats2bfloat162_rn(x0 - f0, x1 - f1);
    l = *reinterpret_cast<uint32_t*>(&lv);
}

// ---------------- bf16x3 mma.sync GEMM (templated BM) ----------------
// C[M,N] = A[M,K] @ B[K,N] ; B row-major [K,Nfull] (+ per-expert stride).
// mode 0: dense rows. mode 1: grouped, rows gathered via g_perm (token=perm/KTOP).
// mode 2: grouped, rows = compacted off[e]+m.
template<int BMv>
__global__ void __launch_bounds__(256, (BMv == 64) ? 2 : 1) mma_gemm(
    const float* __restrict__ A, const float* __restrict__ B, float* __restrict__ C,
    int Kd, int Nfull, long long BexpStride, int mode)
{
    constexpr int A_STAGE = BMv * APITCH;
    constexpr int MT = BMv / 32;          // m-subtiles per warp (warp tile = BMv/2 x 32)
    constexpr int TPR = 256 / BMv;        // loader threads per A row
    constexpr int FPT = 32 / TPR;         // floats per loader thread
    extern __shared__ __align__(16) float smem[];
    float* As = smem;                             // [2][A_STAGE]
    float* Bs = smem + 2*A_STAGE;                 // [2][B_STAGE]
    const float** rowptr = (const float**)(smem + 2*A_STAGE + 2*B_STAGE);

    int tid = threadIdx.x, wid = tid >> 5, lane = tid & 31;
    int n0 = blockIdx.x * BN, m0 = blockIdx.y * BMv;
    int cnt = 1 << 30, off = 0;
    const float* Bm = B;
    if (mode){
        int e = blockIdx.z;
        cnt = g_cnt[e]; if (cnt > CAP) cnt = CAP;
        if (m0 >= cnt) return;
        off = g_off[e];
        Bm = B + (size_t)e * (size_t)BexpStride;
    }
    if (tid < BMv){
        int m = m0 + tid;
        const float* src;
        if (mode == 0)      src = A + (size_t)m * Kd;
        else if (m >= cnt)  src = A;
        else if (mode == 1) src = A + (size_t)(g_perm[off + m] / KTOP) * Kd;
        else                src = A + (size_t)(off + m) * Kd;
        rowptr[tid] = src;
    }
    __syncthreads();

    // loader roles
    int arow = tid / TPR, aoff = (tid % TPR) * FPT;
    int brow = tid >> 3, bch  = tid & 7;           // 8 thr/row, 4x16B chunks

    const int NK = Kd / BKT;

    auto load_stage = [&](int s, int kt){
        int kc = kt * BKT;
        {
            const float* src = rowptr[arow] + kc + aoff;
            uint32_t d = smem_u32(As + s*A_STAGE + arow*APITCH + aoff);
            #pragma unroll
            for (int j = 0; j < FPT/4; j++) CP16(d + 16*j, src + 4*j);
        }
        {
            const float* src = Bm + (size_t)(kc + brow) * Nfull + n0;
            uint32_t d = smem_u32(Bs + s*B_STAGE + brow*BPITCH);
            #pragma unroll
            for (int j = 0; j < 4; j++){
                int f = (bch + 8*j) * 4;
                CP16(d + f*4, src + f);
            }
        }
    };

    float acc[MT][4][4];
    #pragma unroll
    for (int i = 0; i < MT; i++)
        #pragma unroll
        for (int j = 0; j < 4; j++)
            #pragma unroll
            for (int v = 0; v < 4; v++) acc[i][j][v] = 0.f;

    int wm = (wid >> 2) * (BMv/2), wn = (wid & 3) * 32;
    int lg = lane >> 2, lt = lane & 3;

    load_stage(0, 0);
    CP_COMMIT();

    for (int kt = 0; kt < NK; kt++){
        int s = kt & 1;
        if (kt + 1 < NK){
            load_stage(s ^ 1, kt + 1);
            CP_COMMIT();
            CP_WAIT1();
        } else {
            CP_WAIT0();
        }
        __syncthreads();

        const float* as = As + s*A_STAGE;
        const float* bs = Bs + s*B_STAGE;
        #pragma unroll
        for (int ks = 0; ks < 2; ks++){               // two k16 steps per BKT=32
            int kk = ks * 16;
            uint32_t ah[MT][4], al[MT][4], bh[4][2], bl[4][2];
            #pragma unroll
            for (int mt = 0; mt < MT; mt++){
                const float* ap = as + (wm + mt*16 + lg) * APITCH + kk + 2*lt;
                split_pair(ap[0],            ap[1],              ah[mt][0], al[mt][0]);
                split_pair(ap[8*APITCH],     ap[8*APITCH + 1],   ah[mt][1], al[mt][1]);
                split_pair(ap[8],            ap[9],              ah[mt][2], al[mt][2]);
                split_pair(ap[8*APITCH + 8], ap[8*APITCH + 9],   ah[mt][3], al[mt][3]);
            }
            #pragma unroll
            for (int nt = 0; nt < 4; nt++){
                const float* bp = bs + (kk + 2*lt) * BPITCH + wn + nt*8 + lg;
                split_pair(bp[0],          bp[BPITCH],   bh[nt][0], bl[nt][0]);
                split_pair(bp[8*BPITCH],   bp[9*BPITCH], bh[nt][1], bl[nt][1]);
            }
            #pragma unroll
            for (int mt = 0; mt < MT; mt++)
                #pragma unroll
                for (int nt = 0; nt < 4; nt++){
                    mma_bf16(acc[mt][nt], ah[mt], bh[nt]);
                    mma_bf16(acc[mt][nt], ah[mt], bl[nt]);
                    mma_bf16(acc[mt][nt], al[mt], bh[nt]);
                }
        }
        __syncthreads();
    }

    // epilogue
    #pragma unroll
    for (int mt = 0; mt < MT; mt++){
        int r0 = m0 + wm + mt*16 + lg;
        int r1 = r0 + 8;
        bool v0 = (mode == 0) || (r0 < cnt);
        bool v1 = (mode == 0) || (r1 < cnt);
        size_t cr0 = (size_t)((mode == 0) ? r0 : off + r0) * Nfull;
        size_t cr1 = (size_t)((mode == 0) ? r1 : off + r1) * Nfull;
        #pragma unroll
        for (int nt = 0; nt < 4; nt++){
            int col = n0 + wn + nt*8 + 2*lt;
            if (v0) *(float2*)(C + cr0 + col) = make_float2(acc[mt][nt][0], acc[mt][nt][1]);
            if (v1) *(float2*)(C + cr1 + col) = make_float2(acc[mt][nt][2], acc[mt][nt][3]);
        }
    }
}

// ---------------- fused router + grouped top-k (one block per token) ----------------
__global__ __launch_bounds__(256) void router_topk(
    const float* __restrict__ x, const float* __restrict__ gw, const float* __restrict__ bias)
{
    __shared__ float xs[H];
    __shared__ float part[4][64];
    __shared__ float sc[64], sbb[64];
    int t = blockIdx.x;
    ((float4*)xs)[threadIdx.x] = ((const float4*)(x + (size_t)t * H))[threadIdx.x];
    __syncthreads();
    int c = threadIdx.x >> 6, e = threadIdx.x & 63;
    const float* w = gw + (size_t)c * 256 * 64 + e;
    float acc = 0.f;
    #pragma unroll 8
    for (int h = 0; h < 256; h++) acc += xs[c * 256 + h] * w[(size_t)h * 64];
    part[c][e] = acc;
    __syncthreads();
    if (threadIdx.x < 64){
        float l = part[0][e] + part[1][e] + part[2][e] + part[3][e];
        float s = 1.f / (1.f + expf(-l));
        sc[e] = s; sbb[e] = s + bias[e];
    }
    __syncthreads();
    if (threadIdx.x == 0){
        float gs[NGRP];
        #pragma unroll
        for (int g = 0; g < NGRP; g++){
            float m1 = -1e30f, m2 = -1e30f;
            #pragma unroll
            for (int j = 0; j < 8; j++){
                float v = sbb[g * 8 + j];
                if (v > m1){ m2 = m1; m1 = v; } else if (v > m2){ m2 = v; }
            }
            gs[g] = m1 + m2;
        }
        unsigned gsel = 0;
        #pragma unroll
        for (int it = 0; it < TKG; it++){
            float best = -1e30f; int bi = 0;
            for (int g = 0; g < NGRP; g++)
                if (!((gsel >> g) & 1) && gs[g] > best){ best = gs[g]; bi = g; }
            gsel |= 1u << bi;
        }
        unsigned long long used = 0; float wsum = 0.f;
        float wk[KTOP]; int ek[KTOP];
        #pragma unroll
        for (int it = 0; it < KTOP; it++){
            float best = -1e30f; int bi = 0;
            for (int ee = 0; ee < 64; ee++){
                if (((gsel >> (ee >> 3)) & 1) && !((used >> ee) & 1) && sbb[ee] > best){
                    best = sbb[ee]; bi = ee;
                }
            }
            used |= 1ull << bi;
            ek[it] = bi; wk[it] = sc[bi]; wsum += sc[bi];
        }
        float inv = 1.f / wsum;
        #pragma unroll
        for (int k = 0; k < KTOP; k++){
            g_eidx[t * KTOP + k] = ek[k];
            g_w[t * KTOP + k] = wk[k] * inv;
        }
    }
}

// ---------------- silu(g)*u ----------------
__global__ void silu_mul_k(const float* __restrict__ gu, float* __restrict__ act,
                           int rows, int half)
{
    int i = blockIdx.x * blockDim.x + threadIdx.x;
    if (i >= rows * half) return;
    int r = i / half, j = i - r * half;
    float g = gu[(size_t)r * 2 * half + j];
    float u = gu[(size_t)r * 2 * half + half + j];
    act[i] = (g / (1.f + expf(-g))) * u;
}

// ---------------- fused dispatch (one block) ----------------
__global__ __launch_bounds__(1024) void dispatch_k()
{
    int tid = threadIdx.x;
    if (tid < E) g_cnt[tid] = 0;
    __syncthreads();
    for (int a = tid; a < A_TOT; a += 1024)
        g_slot[a] = atomicAdd(&g_cnt[g_eidx[a]], 1);
    __syncthreads();
    if (tid == 0){
        int s = 0;
        for (int e = 0; e < E; e++){
            g_off[e] = s;
            int c = g_cnt[e];
            s += (c > CAP) ? CAP : c;
        }
        g_off[E] = s;
    }
    __syncthreads();
    for (int a = tid; a < A_TOT; a += 1024){
        int e = g_eidx[a], sl = g_slot[a];
        if (sl < CAP){ int r = g_off[e] + sl; g_perm[r] = a; g_rowpos[a] = r; }
        else g_rowpos[a] = -1;
    }
}

// ---------------- combine ----------------
__global__ __launch_bounds__(256) void combine_k(float* __restrict__ out)
{
    int t = blockIdx.x;
    int h0 = threadIdx.x * 4;
    float4 acc = *(float4*)&out[(size_t)t * H + h0];
    #pragma unroll
    for (int k = 0; k < KTOP; k++){
        int a = t * KTOP + k;
        int r = g_rowpos[a];
        if (r >= 0){
            float w = 2.5f * g_w[a];
            float4 y = *(const float4*)&g_y[(size_t)r * H + h0];
            acc.x += w * y.x; acc.y += w * y.y; acc.z += w * y.z; acc.w += w * y.w;
        }
    }
    *(float4*)&out[(size_t)t * H + h0] = acc;
}

// ---------------- launch ----------------
extern "C" void kernel_launch(void* const* d_in, const int* in_sizes, int n_in,
                              void* d_out, int out_size)
{
    const float* x      = (const float*)d_in[0];  // [T,H]
    const float* gate_w = (const float*)d_in[1];  // [H,E]
    const float* e_bias = (const float*)d_in[2];  // [E]
    const float* w_gu   = (const float*)d_in[3];  // [E,H,2I]
    const float* w_dn   = (const float*)d_in[4];  // [E,I,H]
    const float* ws_gu  = (const float*)d_in[5];  // [H,2048]
    const float* ws_dn  = (const float*)d_in[6];  // [1024,H]
    float* out = (float*)d_out;

    float *p_guS, *p_actS, *p_gu, *p_act, *p_y;
    cudaGetSymbolAddress((void**)&p_guS,  g_guS);
    cudaGetSymbolAddress((void**)&p_actS, g_actS);
    cudaGetSymbolAddress((void**)&p_gu,   g_gu);
    cudaGetSymbolAddress((void**)&p_act,  g_act);
    cudaGetSymbolAddress((void**)&p_y,    g_y);

    const int SMEM128 = (2*(128*APITCH) + 2*B_STAGE)*4 + 128*8;
    const int SMEM64  = (2*(64*APITCH)  + 2*B_STAGE)*4 + 64*8;
    cudaFuncSetAttribute(mma_gemm<128>, cudaFuncAttributeMaxDynamicSharedMemorySize, SMEM128);
    cudaFuncSetAttribute(mma_gemm<64>,  cudaFuncAttributeMaxDynamicSharedMemorySize, SMEM64);

    // router + dispatch
    router_topk<<<T, 256>>>(x, gate_w, e_bias);
    dispatch_k<<<1, 1024>>>();

    // shared experts MLP -> out
    mma_gemm<128><<<dim3(NSH_2 / BN, T / 128, 1), 256, SMEM128>>>(
        x, ws_gu, p_guS, H, NSH_2, 0, 0);
    silu_mul_k<<<(T * NSH_HALF + 255) / 256, 256>>>(p_guS, p_actS, T, NSH_HALF);
    mma_gemm<64><<<dim3(H / BN, T / 64, 1), 256, SMEM64>>>(
        p_actS, ws_dn, out, NSH_HALF, H, 0, 0);

    // routed experts
    mma_gemm<64><<<dim3(TWO_I / BN, CAP / 64, E), 256, SMEM64>>>(
        x, w_gu, p_gu, H, TWO_I, (long long)H * TWO_I, 1);
    silu_mul_k<<<(A_TOT * ISZ + 255) / 256, 256>>>(p_gu, p_act, A_TOT, ISZ);
    mma_gemm<64><<<dim3(H / BN, CAP / 64, E), 256, SMEM64>>>(
        p_act, w_dn, p_y, ISZ, H, (long long)ISZ * H, 2);

    // combine
    combine_k<<<T, 256>>>(out);
}

// round 8
// speedup vs baseline: 1.9685x; 1.0368x over previous
#include <cuda_runtime.h>
#include <cuda_bf16.h>
#include <cstdint>
#include <math.h>

#define T 1024
#define H 1024
#define E 64
#define ISZ 512
#define TWO_I 1024
#define KTOP 6
#define NGRP 8
#define TKG 3
#define CAP 256
#define A_TOT (T*KTOP)
#define NSH_HALF 1024
#define NSH_2 2048

// down-GEMM tiling
#define BN 128
#define BKT 32
#define APITCH 36
#define BPITCH 136
#define B_STAGE (BKT*BPITCH)
// fused gate_up tiling (per-half BN=64)
#define BNH 64
#define BHPITCH 72
#define BH_STAGE (BKT*BHPITCH)

// ---------------- scratch ----------------
__device__ float g_w[A_TOT];
__device__ int   g_eidx[A_TOT];
__device__ int   g_cnt[E];
__device__ int   g_off[E+1];
__device__ int   g_slot[A_TOT];
__device__ int   g_perm[A_TOT];
__device__ int   g_rowpos[A_TOT];
__device__ float g_actS[T*NSH_HALF];
__device__ float g_act[A_TOT*ISZ];
__device__ float g_y[A_TOT*H];

// ---------------- PTX helpers ----------------
__device__ __forceinline__ uint32_t smem_u32(const void* p){
    uint32_t a;
    asm("{ .reg .u64 t; cvta.to.shared.u64 t, %1; cvt.u32.u64 %0, t; }" : "=r"(a) : "l"(p));
    return a;
}
#define CP16(d,s) asm volatile("cp.async.cg.shared.global [%0], [%1], 16;" :: "r"(d), "l"(s))
#define CP_COMMIT() asm volatile("cp.async.commit_group;" ::: "memory")
#define CP_WAIT1()  asm volatile("cp.async.wait_group 1;" ::: "memory")
#define CP_WAIT0()  asm volatile("cp.async.wait_group 0;" ::: "memory")

__device__ __forceinline__ void mma_bf16(float* c, const uint32_t* a, const uint32_t* b){
    asm volatile(
        "mma.sync.aligned.m16n8k16.row.col.f32.bf16.bf16.f32 "
        "{%0,%1,%2,%3}, {%4,%5,%6,%7}, {%8,%9}, {%0,%1,%2,%3};"
        : "+f"(c[0]), "+f"(c[1]), "+f"(c[2]), "+f"(c[3])
        : "r"(a[0]), "r"(a[1]), "r"(a[2]), "r"(a[3]), "r"(b[0]), "r"(b[1]));
}

__device__ __forceinline__ void split_pair(float x0, float x1, uint32_t& h, uint32_t& l){
    uint32_t u0 = __float_as_uint(x0), u1 = __float_as_uint(x1);
    h = __byte_perm(u0, u1, 0x7632);
    float f0 = __uint_as_float(u0 & 0xFFFF0000u);
    float f1 = __uint_as_float(u1 & 0xFFFF0000u);
    __nv_bfloat162 lv = __floats2bfloat162_rn(x0 - f0, x1 - f1);
    l = *reinterpret_cast<uint32_t*>(&lv);
}

__device__ __forceinline__ float silu_mul(float g, float u){
    return (g / (1.f + expf(-g))) * u;
}

// ---------------- down-proj bf16x3 GEMM (BM=64, BN=128) ----------------
// mode 0: dense rows. mode 2: grouped rows = off[e]+m.
__global__ void __launch_bounds__(256, 2) mma_gemm(
    const float* __restrict__ A, const float* __restrict__ B, float* __restrict__ C,
    int Kd, int Nfull, long long BexpStride, int mode)
{
    constexpr int BMv = 64;
    constexpr int A_STAGE = BMv * APITCH;
    constexpr int MT = 2;
    extern __shared__ __align__(16) float smem[];
    float* As = smem;
    float* Bs = smem + 2*A_STAGE;
    const float** rowptr = (const float**)(smem + 2*A_STAGE + 2*B_STAGE);

    int tid = threadIdx.x, wid = tid >> 5, lane = tid & 31;
    int n0 = blockIdx.x * BN, m0 = blockIdx.y * BMv;
    int cnt = 1 << 30, off = 0;
    const float* Bm = B;
    if (mode){
        int e = blockIdx.z;
        cnt = g_cnt[e]; if (cnt > CAP) cnt = CAP;
        if (m0 >= cnt) return;
        off = g_off[e];
        Bm = B + (size_t)e * (size_t)BexpStride;
    }
    if (tid < BMv){
        int m = m0 + tid;
        const float* src;
        if (mode == 0)      src = A + (size_t)m * Kd;
        else if (m >= cnt)  src = A;
        else                src = A + (size_t)(off + m) * Kd;
        rowptr[tid] = src;
    }
    __syncthreads();

    int arow = tid >> 2, aoff = (tid & 3) * 8;
    int brow = tid >> 3, bch  = tid & 7;
    const int NK = Kd / BKT;

    auto load_stage = [&](int s, int kt){
        int kc = kt * BKT;
        {
            const float* src = rowptr[arow] + kc + aoff;
            uint32_t d = smem_u32(As + s*A_STAGE + arow*APITCH + aoff);
            CP16(d, src); CP16(d + 16, src + 4);
        }
        {
            const float* src = Bm + (size_t)(kc + brow) * Nfull + n0;
            uint32_t d = smem_u32(Bs + s*B_STAGE + brow*BPITCH);
            #pragma unroll
            for (int j = 0; j < 4; j++){
                int f = (bch + 8*j) * 4;
                CP16(d + f*4, src + f);
            }
        }
    };

    float acc[MT][4][4];
    #pragma unroll
    for (int i = 0; i < MT; i++)
        #pragma unroll
        for (int j = 0; j < 4; j++)
            #pragma unroll
            for (int v = 0; v < 4; v++) acc[i][j][v] = 0.f;

    int wm = (wid >> 2) * 32, wn = (wid & 3) * 32;
    int lg = lane >> 2, lt = lane & 3;

    load_stage(0, 0);
    CP_COMMIT();

    for (int kt = 0; kt < NK; kt++){
        int s = kt & 1;
        if (kt + 1 < NK){
            load_stage(s ^ 1, kt + 1);
            CP_COMMIT();
            CP_WAIT1();
        } else {
            CP_WAIT0();
        }
        __syncthreads();

        const float* as = As + s*A_STAGE;
        const float* bs = Bs + s*B_STAGE;
        #pragma unroll
        for (int ks = 0; ks < 2; ks++){
            int kk = ks * 16;
            uint32_t ah[MT][4], al[MT][4], bh[4][2], bl[4][2];
            #pragma unroll
            for (int mt = 0; mt < MT; mt++){
                const float* ap = as + (wm + mt*16 + lg) * APITCH + kk + 2*lt;
                split_pair(ap[0],            ap[1],              ah[mt][0], al[mt][0]);
                split_pair(ap[8*APITCH],     ap[8*APITCH + 1],   ah[mt][1], al[mt][1]);
                split_pair(ap[8],            ap[9],              ah[mt][2], al[mt][2]);
                split_pair(ap[8*APITCH + 8], ap[8*APITCH + 9],   ah[mt][3], al[mt][3]);
            }
            #pragma unroll
            for (int nt = 0; nt < 4; nt++){
                const float* bp = bs + (kk + 2*lt) * BPITCH + wn + nt*8 + lg;
                split_pair(bp[0],          bp[BPITCH],   bh[nt][0], bl[nt][0]);
                split_pair(bp[8*BPITCH],   bp[9*BPITCH], bh[nt][1], bl[nt][1]);
            }
            #pragma unroll
            for (int mt = 0; mt < MT; mt++)
                #pragma unroll
                for (int nt = 0; nt < 4; nt++){
                    mma_bf16(acc[mt][nt], ah[mt], bh[nt]);
                    mma_bf16(acc[mt][nt], ah[mt], bl[nt]);
                    mma_bf16(acc[mt][nt], al[mt], bh[nt]);
                }
        }
        __syncthreads();
    }

    #pragma unroll
    for (int mt = 0; mt < MT; mt++){
        int r0 = m0 + wm + mt*16 + lg;
        int r1 = r0 + 8;
        bool v0 = (mode == 0) || (r0 < cnt);
        bool v1 = (mode == 0) || (r1 < cnt);
        size_t cr0 = (size_t)((mode == 0) ? r0 : off + r0) * Nfull;
        size_t cr1 = (size_t)((mode == 0) ? r1 : off + r1) * Nfull;
        #pragma unroll
        for (int nt = 0; nt < 4; nt++){
            int col = n0 + wn + nt*8 + 2*lt;
            if (v0) *(float2*)(C + cr0 + col) = make_float2(acc[mt][nt][0], acc[mt][nt][1]);
            if (v1) *(float2*)(C + cr1 + col) = make_float2(acc[mt][nt][2], acc[mt][nt][3]);
        }
    }
}

// ---------------- fused gate_up + silu GEMM (BM=64, two 64-wide halves) ----------------
// Computes g = A@B[:, n0..n0+64), u = A@B[:, n0+Nfull/2 ...), writes silu(g)*u
// to Cact[row, n0..n0+64) with row pitch halfN = Nfull/2.
// mode 0: dense rows (shared experts). mode 1: grouped, gather via g_perm.
__global__ void __launch_bounds__(256, 2) mma_gemm_silu(
    const float* __restrict__ A, const float* __restrict__ B, float* __restrict__ Cact,
    int Kd, int Nfull, long long BexpStride, int mode)
{
    constexpr int BMv = 64;
    constexpr int A_STAGE = BMv * APITCH;
    constexpr int MT = 2;
    const int halfN = Nfull >> 1;
    extern __shared__ __align__(16) float smem[];
    float* As = smem;                                  // [2][A_STAGE]
    float* Bs = smem + 2*A_STAGE;                      // [2][2*BH_STAGE]
    const float** rowptr = (const float**)(smem + 2*A_STAGE + 4*BH_STAGE);

    int tid = threadIdx.x, wid = tid >> 5, lane = tid & 31;
    int n0 = blockIdx.x * BNH, m0 = blockIdx.y * BMv;
    int cnt = 1 << 30, off = 0;
    const float* Bm = B;
    if (mode){
        int e = blockIdx.z;
        cnt = g_cnt[e]; if (cnt > CAP) cnt = CAP;
        if (m0 >= cnt) return;
        off = g_off[e];
        Bm = B + (size_t)e * (size_t)BexpStride;
    }
    if (tid < BMv){
        int m = m0 + tid;
        const float* src;
        if (mode == 0)      src = A + (size_t)m * Kd;
        else if (m >= cnt)  src = A;
        else                src = A + (size_t)(g_perm[off + m] / KTOP) * Kd;
        rowptr[tid] = src;
    }
    __syncthreads();

    int arow = tid >> 2, aoff = (tid & 3) * 8;
    int brow = tid >> 3, bcol = (tid & 7) * 8;     // 8 thr/row, 8 floats each (64 cols)
    const int NK = Kd / BKT;

    auto load_stage = [&](int s, int kt){
        int kc = kt * BKT;
        {
            const float* src = rowptr[arow] + kc + aoff;
            uint32_t d = smem_u32(As + s*A_STAGE + arow*APITCH + aoff);
            CP16(d, src); CP16(d + 16, src + 4);
        }
        {
            const float* srcg = Bm + (size_t)(kc + brow) * Nfull + n0 + bcol;
            const float* srcu = srcg + halfN;
            uint32_t dg = smem_u32(Bs + s*2*BH_STAGE + brow*BHPITCH + bcol);
            uint32_t du = dg + BH_STAGE*4;
            CP16(dg, srcg); CP16(dg + 16, srcg + 4);
            CP16(du, srcu); CP16(du + 16, srcu + 4);
        }
    };

    float acc[MT][2][2][4];   // [m][half][nt][v]
    #pragma unroll
    for (int i = 0; i < MT; i++)
        #pragma unroll
        for (int hh = 0; hh < 2; hh++)
            #pragma unroll
            for (int j = 0; j < 2; j++)
                #pragma unroll
                for (int v = 0; v < 4; v++) acc[i][hh][j][v] = 0.f;

    int wm = (wid >> 2) * 32, wn = (wid & 3) * 16;
    int lg = lane >> 2, lt = lane & 3;

    load_stage(0, 0);
    CP_COMMIT();

    for (int kt = 0; kt < NK; kt++){
        int s = kt & 1;
        if (kt + 1 < NK){
            load_stage(s ^ 1, kt + 1);
            CP_COMMIT();
            CP_WAIT1();
        } else {
            CP_WAIT0();
        }
        __syncthreads();

        const float* as = As + s*A_STAGE;
        const float* bs = Bs + s*2*BH_STAGE;
        #pragma unroll
        for (int ks = 0; ks < 2; ks++){
            int kk = ks * 16;
            uint32_t ah[MT][4], al[MT][4], bh[2][2][2], bl[2][2][2];
            #pragma unroll
            for (int mt = 0; mt < MT; mt++){
                const float* ap = as + (wm + mt*16 + lg) * APITCH + kk + 2*lt;
                split_pair(ap[0],            ap[1],              ah[mt][0], al[mt][0]);
                split_pair(ap[8*APITCH],     ap[8*APITCH + 1],   ah[mt][1], al[mt][1]);
                split_pair(ap[8],            ap[9],              ah[mt][2], al[mt][2]);
                split_pair(ap[8*APITCH + 8], ap[8*APITCH + 9],   ah[mt][3], al[mt][3]);
            }
            #pragma unroll
            for (int hh = 0; hh < 2; hh++){
                #pragma unroll
                for (int nt = 0; nt < 2; nt++){
                    const float* bp = bs + hh*BH_STAGE + (kk + 2*lt) * BHPITCH + wn + nt*8 + lg;
                    split_pair(bp[0],          bp[BHPITCH],   bh[hh][nt][0], bl[hh][nt][0]);
                    split_pair(bp[8*BHPITCH],  bp[9*BHPITCH], bh[hh][nt][1], bl[hh][nt][1]);
                }
            }
            #pragma unroll
            for (int mt = 0; mt < MT; mt++)
                #pragma unroll
                for (int hh = 0; hh < 2; hh++)
                    #pragma unroll
                    for (int nt = 0; nt < 2; nt++){
                        mma_bf16(acc[mt][hh][nt], ah[mt], bh[hh][nt]);
                        mma_bf16(acc[mt][hh][nt], ah[mt], bl[hh][nt]);
                        mma_bf16(acc[mt][hh][nt], al[mt], bh[hh][nt]);
                    }
        }
        __syncthreads();
    }

    #pragma unroll
    for (int mt = 0; mt < MT; mt++){
        int r0 = m0 + wm + mt*16 + lg;
        int r1 = r0 + 8;
        bool v0 = (mode == 0) || (r0 < cnt);
        bool v1 = (mode == 0) || (r1 < cnt);
        size_t cr0 = (size_t)((mode == 0) ? r0 : off + r0) * halfN;
        size_t cr1 = (size_t)((mode == 0) ? r1 : off + r1) * halfN;
        #pragma unroll
        for (int nt = 0; nt < 2; nt++){
            int col = n0 + wn + nt*8 + 2*lt;
            if (v0){
                float2 o = make_float2(silu_mul(acc[mt][0][nt][0], acc[mt][1][nt][0]),
                                       silu_mul(acc[mt][0][nt][1], acc[mt][1][nt][1]));
                *(float2*)(Cact + cr0 + col) = o;
            }
            if (v1){
                float2 o = make_float2(silu_mul(acc[mt][0][nt][2], acc[mt][1][nt][2]),
                                       silu_mul(acc[mt][0][nt][3], acc[mt][1][nt][3]));
                *(float2*)(Cact + cr1 + col) = o;
            }
        }
    }
}

// ---------------- router: 8 tokens per block ----------------
__global__ __launch_bounds__(256) void router_topk(
    const float* __restrict__ x, const float* __restrict__ gw, const float* __restrict__ bias)
{
    __shared__ float xs[8][H];
    __shared__ float part[4][8][64];
    __shared__ float sc[8][64], sbb[8][64];
    int t0 = blockIdx.x * 8;
    // load 8 token rows
    for (int i = threadIdx.x; i < 8 * (H/4); i += 256){
        int tk = i / (H/4), j = i % (H/4);
        ((float4*)xs[tk])[j] = ((const float4*)(x + (size_t)(t0 + tk) * H))[j];
    }
    __syncthreads();
    int c = threadIdx.x >> 6, e = threadIdx.x & 63;
    float acc[8];
    #pragma unroll
    for (int tk = 0; tk < 8; tk++) acc[tk] = 0.f;
    const float* w = gw + (size_t)c * 256 * 64 + e;
    for (int h = 0; h < 256; h++){
        float wv = w[(size_t)h * 64];
        float* xcol = &xs[0][c * 256 + h];
        #pragma unroll
        for (int tk = 0; tk < 8; tk++) acc[tk] += xcol[tk * H] * wv;
    }
    #pragma unroll
    for (int tk = 0; tk < 8; tk++) part[c][tk][e] = acc[tk];
    __syncthreads();
    // 512 cells (8 tk x 64 e) over 256 threads
    for (int i = threadIdx.x; i < 512; i += 256){
        int tk = i >> 6, ee = i & 63;
        float l = part[0][tk][ee] + part[1][tk][ee] + part[2][tk][ee] + part[3][tk][ee];
        float s = 1.f / (1.f + expf(-l));
        sc[tk][ee] = s; sbb[tk][ee] = s + bias[ee];
    }
    __syncthreads();
    if (threadIdx.x < 8){
        int tk = threadIdx.x;
        int t = t0 + tk;
        float gs[NGRP];
        #pragma unroll
        for (int g = 0; g < NGRP; g++){
            float m1 = -1e30f, m2 = -1e30f;
            #pragma unroll
            for (int j = 0; j < 8; j++){
                float v = sbb[tk][g * 8 + j];
                if (v > m1){ m2 = m1; m1 = v; } else if (v > m2){ m2 = v; }
            }
            gs[g] = m1 + m2;
        }
        unsigned gsel = 0;
        #pragma unroll
        for (int it = 0; it < TKG; it++){
            float best = -1e30f; int bi = 0;
            for (int g = 0; g < NGRP; g++)
                if (!((gsel >> g) & 1) && gs[g] > best){ best = gs[g]; bi = g; }
            gsel |= 1u << bi;
        }
        unsigned long long used = 0; float wsum = 0.f;
        float wk[KTOP]; int ek[KTOP];
        #pragma unroll
        for (int it = 0; it < KTOP; it++){
            float best = -1e30f; int bi = 0;
            for (int ee = 0; ee < 64; ee++){
                if (((gsel >> (ee >> 3)) & 1) && !((used >> ee) & 1) && sbb[tk][ee] > best){
                    best = sbb[tk][ee]; bi = ee;
                }
            }
            used |= 1ull << bi;
            ek[it] = bi; wk[it] = sc[tk][bi]; wsum += sc[tk][bi];
        }
        float inv = 1.f / wsum;
        #pragma unroll
        for (int k = 0; k < KTOP; k++){
            g_eidx[t * KTOP + k] = ek[k];
            g_w[t * KTOP + k] = wk[k] * inv;
        }
    }
}

// ---------------- fused dispatch (one block) ----------------
__global__ __launch_bounds__(1024) void dispatch_k()
{
    int tid = threadIdx.x;
    if (tid < E) g_cnt[tid] = 0;
    __syncthreads();
    for (int a = tid; a < A_TOT; a += 1024)
        g_slot[a] = atomicAdd(&g_cnt[g_eidx[a]], 1);
    __syncthreads();
    if (tid == 0){
        int s = 0;
        for (int e = 0; e < E; e++){
            g_off[e] = s;
            int c = g_cnt[e];
            s += (c > CAP) ? CAP : c;
        }
        g_off[E] = s;
    }
    __syncthreads();
    for (int a = tid; a < A_TOT; a += 1024){
        int e = g_eidx[a], sl = g_slot[a];
        if (sl < CAP){ int r = g_off[e] + sl; g_perm[r] = a; g_rowpos[a] = r; }
        else g_rowpos[a] = -1;
    }
}

// ---------------- combine ----------------
__global__ __launch_bounds__(256) void combine_k(float* __restrict__ out)
{
    int t = blockIdx.x;
    int h0 = threadIdx.x * 4;
    float4 acc = *(float4*)&out[(size_t)t * H + h0];
    #pragma unroll
    for (int k = 0; k < KTOP; k++){
        int a = t * KTOP + k;
        int r = g_rowpos[a];
        if (r >= 0){
            float w = 2.5f * g_w[a];
            float4 y = *(const float4*)&g_y[(size_t)r * H + h0];
            acc.x += w * y.x; acc.y += w * y.y; acc.z += w * y.z; acc.w += w * y.w;
        }
    }
    *(float4*)&out[(size_t)t * H + h0] = acc;
}

// ---------------- launch ----------------
extern "C" void kernel_launch(void* const* d_in, const int* in_sizes, int n_in,
                              void* d_out, int out_size)
{
    const float* x      = (const float*)d_in[0];  // [T,H]
    const float* gate_w = (const float*)d_in[1];  // [H,E]
    const float* e_bias = (const float*)d_in[2];  // [E]
    const float* w_gu   = (const float*)d_in[3];  // [E,H,2I]
    const float* w_dn   = (const float*)d_in[4];  // [E,I,H]
    const float* ws_gu  = (const float*)d_in[5];  // [H,2048]
    const float* ws_dn  = (const float*)d_in[6];  // [1024,H]
    float* out = (float*)d_out;

    float *p_actS, *p_act, *p_y;
    cudaGetSymbolAddress((void**)&p_actS, g_actS);
    cudaGetSymbolAddress((void**)&p_act,  g_act);
    cudaGetSymbolAddress((void**)&p_y,    g_y);

    const int SMEM_DN = (2*(64*APITCH) + 2*B_STAGE)*4 + 64*8;
    const int SMEM_GU = (2*(64*APITCH) + 4*BH_STAGE)*4 + 64*8;
    cudaFuncSetAttribute(mma_gemm,      cudaFuncAttributeMaxDynamicSharedMemorySize, SMEM_DN);
    cudaFuncSetAttribute(mma_gemm_silu, cudaFuncAttributeMaxDynamicSharedMemorySize, SMEM_GU);

    // router + dispatch
    router_topk<<<T/8, 256>>>(x, gate_w, e_bias);
    dispatch_k<<<1, 1024>>>();

    // shared experts: fused gate_up+silu -> actS, then down -> out
    mma_gemm_silu<<<dim3(NSH_HALF / BNH, T / 64, 1), 256, SMEM_GU>>>(
        x, ws_gu, p_actS, H, NSH_2, 0, 0);
    mma_gemm<<<dim3(H / BN, T / 64, 1), 256, SMEM_DN>>>(
        p_actS, ws_dn, out, NSH_HALF, H, 0, 0);

    // routed experts: fused gate_up+silu (gathered) -> act, down -> y
    mma_gemm_silu<<<dim3(ISZ / BNH, CAP / 64, E), 256, SMEM_GU>>>(
        x, w_gu, p_act, H, TWO_I, (long long)H * TWO_I, 1);
    mma_gemm<<<dim3(H / BN, CAP / 64, E), 256, SMEM_DN>>>(
        p_act, w_dn, p_y, ISZ, H, (long long)ISZ * H, 2);

    // combine
    combine_k<<<T, 256>>>(out);
}

// round 9
// speedup vs baseline: 2.2033x; 1.1193x over previous
#include <cuda_runtime.h>
#include <cuda_bf16.h>
#include <cstdint>
#include <math.h>

#define T 1024
#define H 1024
#define E 64
#define ISZ 512
#define TWO_I 1024
#define KTOP 6
#define NGRP 8
#define TKG 3
#define CAP 256
#define A_TOT (T*KTOP)
#define NSH_HALF 1024
#define NSH_2 2048

#define BKT 32
// packed A: [64 rows][APW u32], interleaved (hi,lo) bf16x2 pairs along k
#define APW 40
#define A_SZ (64*APW)
// packed B: [16 k2][2*BN + 8 u32]
#define BNH 64
#define BPWH (2*BNH + 8)       // 136
#define BH_SZ (16*BPWH)

// ---------------- scratch ----------------
__device__ float g_w[A_TOT];
__device__ int   g_eidx[A_TOT];
__device__ int   g_cnt[E];
__device__ int   g_off[E+1];
__device__ int   g_slot[A_TOT];
__device__ int   g_perm[A_TOT];
__device__ int   g_rowpos[A_TOT];
__device__ float g_actS[T*NSH_HALF];
__device__ float g_act[A_TOT*ISZ];
__device__ float g_y[A_TOT*H];

// ---------------- helpers ----------------
__device__ __forceinline__ void mma_bf16(float* c, const uint32_t* a, const uint32_t* b){
    asm volatile(
        "mma.sync.aligned.m16n8k16.row.col.f32.bf16.bf16.f32 "
        "{%0,%1,%2,%3}, {%4,%5,%6,%7}, {%8,%9}, {%0,%1,%2,%3};"
        : "+f"(c[0]), "+f"(c[1]), "+f"(c[2]), "+f"(c[3])
        : "r"(a[0]), "r"(a[1]), "r"(a[2]), "r"(a[3]), "r"(b[0]), "r"(b[1]));
}

// hi = truncate-to-bf16 (x = hi + lo_exact), lo = rn-bf16(x - hi). packed pairs.
__device__ __forceinline__ void split_pair(float x0, float x1, uint32_t& h, uint32_t& l){
    uint32_t u0 = __float_as_uint(x0), u1 = __float_as_uint(x1);
    h = __byte_perm(u0, u1, 0x7632);
    float f0 = __uint_as_float(u0 & 0xFFFF0000u);
    float f1 = __uint_as_float(u1 & 0xFFFF0000u);
    __nv_bfloat162 lv = __floats2bfloat162_rn(x0 - f0, x1 - f1);
    l = *reinterpret_cast<uint32_t*>(&lv);
}

__device__ __forceinline__ float silu_mul(float g, float u){
    return (g / (1.f + expf(-g))) * u;
}

// ---------------- down-proj bf16x3 GEMM (BM=64, templated BN) ----------------
// mode 0: dense rows. mode 2: grouped rows = off[e]+m.
template<int BNv>
__global__ void __launch_bounds__(256, 2) mma_gemm(
    const float* __restrict__ A, const float* __restrict__ B, float* __restrict__ C,
    int Kd, int Nfull, long long BexpStride, int mode)
{
    constexpr int BPW  = 2*BNv + 8;
    constexpr int B_SZ = 16*BPW;
    constexpr int CPB  = BNv/16;        // cols per B-loader thread
    constexpr int NT   = BNv/32;        // n-subtiles per warp
    extern __shared__ __align__(16) uint32_t smemu[];
    uint32_t* As = smemu;                       // [2][A_SZ]
    uint32_t* Bs = smemu + 2*A_SZ;              // [2][B_SZ]
    const float** rowptr = (const float**)(smemu + 2*A_SZ + 2*B_SZ);

    int tid = threadIdx.x, wid = tid >> 5, lane = tid & 31;
    int n0 = blockIdx.x * BNv, m0 = blockIdx.y * 64;
    int cnt = 1 << 30, off = 0;
    const float* Bm = B;
    if (mode){
        int e = blockIdx.z;
        cnt = g_cnt[e]; if (cnt > CAP) cnt = CAP;
        if (m0 >= cnt) return;
        off = g_off[e];
        Bm = B + (size_t)e * (size_t)BexpStride;
    }
    if (tid < 64){
        int m = m0 + tid;
        const float* src;
        if (mode == 0)      src = A + (size_t)m * Kd;
        else if (m >= cnt)  src = A;
        else                src = A + (size_t)(off + m) * Kd;
        rowptr[tid] = src;
    }
    __syncthreads();

    // loader geometry
    int arow = tid >> 2, aoff = (tid & 3) * 8;
    int k2l = tid >> 4, colg = tid & 15;
    int cb = colg * CPB;
    const float* aptr = rowptr[arow] + aoff;
    const float* bptr0 = Bm + (size_t)(2*k2l) * Nfull + n0 + cb;
    const float* bptr1 = bptr0 + Nfull;

    const int NK = Kd / BKT;
    float4 pa0, pa1;
    float4 pb[CPB/2];   // row r0: CPB floats
    float4 qb[CPB/2];   // row r1: CPB floats

    auto ldg = [&](int kt){
        size_t kc = (size_t)kt * BKT;
        pa0 = *(const float4*)(aptr + kc);
        pa1 = *(const float4*)(aptr + kc + 4);
        size_t bo = kc * Nfull;
        #pragma unroll
        for (int j = 0; j < CPB/2; j++){
            pb[j] = *(const float4*)(bptr0 + bo + 4*j);
            qb[j] = *(const float4*)(bptr1 + bo + 4*j);
        }
    };

    auto sts = [&](int s){
        uint32_t o[8];
        split_pair(pa0.x, pa0.y, o[0], o[1]);
        split_pair(pa0.z, pa0.w, o[2], o[3]);
        split_pair(pa1.x, pa1.y, o[4], o[5]);
        split_pair(pa1.z, pa1.w, o[6], o[7]);
        uint32_t* ad = As + s*A_SZ + arow*APW + aoff;
        *(uint4*)ad       = *(uint4*)&o[0];
        *(uint4*)(ad + 4) = *(uint4*)&o[4];
        uint32_t b[2*CPB];
        #pragma unroll
        for (int j = 0; j < CPB/2; j++){
            split_pair(pb[j].x, qb[j].x, b[8*j+0], b[8*j+1]);
            split_pair(pb[j].y, qb[j].y, b[8*j+2], b[8*j+3]);
            split_pair(pb[j].z, qb[j].z, b[8*j+4], b[8*j+5]);
            split_pair(pb[j].w, qb[j].w, b[8*j+6], b[8*j+7]);
        }
        uint32_t* bd = Bs + s*B_SZ + k2l*BPW + 2*cb;
        #pragma unroll
        for (int j = 0; j < (2*CPB)/4; j++)
            *(uint4*)(bd + 4*j) = *(uint4*)&b[4*j];
    };

    float acc[2][NT][4];
    #pragma unroll
    for (int i = 0; i < 2; i++)
        #pragma unroll
        for (int j = 0; j < NT; j++)
            #pragma unroll
            for (int v = 0; v < 4; v++) acc[i][j][v] = 0.f;

    int wm = (wid >> 2) * 32, wn = (wid & 3) * (NT*8);
    int lg = lane >> 2, lt = lane & 3;

    ldg(0);
    for (int kt = 0; kt < NK; kt++){
        int s = kt & 1;
        sts(s);
        __syncthreads();
        if (kt + 1 < NK) ldg(kt + 1);

        const uint32_t* as = As + s*A_SZ;
        const uint32_t* bs = Bs + s*B_SZ;
        #pragma unroll
        for (int ks = 0; ks < 2; ks++){
            int k2o = ks * 8;
            uint32_t ah[2][4], al[2][4], bh[NT][2], bl[NT][2];
            #pragma unroll
            for (int mt = 0; mt < 2; mt++){
                int row = wm + mt*16 + lg;
                uint2 v0 = *(const uint2*)(as + row*APW     + 2*(k2o+lt));
                uint2 v1 = *(const uint2*)(as + (row+8)*APW + 2*(k2o+lt));
                uint2 v2 = *(const uint2*)(as + row*APW     + 2*(k2o+4+lt));
                uint2 v3 = *(const uint2*)(as + (row+8)*APW + 2*(k2o+4+lt));
                ah[mt][0]=v0.x; al[mt][0]=v0.y;
                ah[mt][1]=v1.x; al[mt][1]=v1.y;
                ah[mt][2]=v2.x; al[mt][2]=v2.y;
                ah[mt][3]=v3.x; al[mt][3]=v3.y;
            }
            #pragma unroll
            for (int nt = 0; nt < NT; nt++){
                int n = wn + nt*8 + lg;
                uint2 w0 = *(const uint2*)(bs + (k2o+lt)*BPW   + 2*n);
                uint2 w1 = *(const uint2*)(bs + (k2o+4+lt)*BPW + 2*n);
                bh[nt][0]=w0.x; bl[nt][0]=w0.y;
                bh[nt][1]=w1.x; bl[nt][1]=w1.y;
            }
            #pragma unroll
            for (int mt = 0; mt < 2; mt++)
                #pragma unroll
                for (int nt = 0; nt < NT; nt++){
                    mma_bf16(acc[mt][nt], ah[mt], bh[nt]);
                    mma_bf16(acc[mt][nt], ah[mt], bl[nt]);
                    mma_bf16(acc[mt][nt], al[mt], bh[nt]);
                }
        }
        __syncthreads();
    }

    #pragma unroll
    for (int mt = 0; mt < 2; mt++){
        int r0 = m0 + wm + mt*16 + lg;
        int r1 = r0 + 8;
        bool v0 = (mode == 0) || (r0 < cnt);
        bool v1 = (mode == 0) || (r1 < cnt);
        size_t cr0 = (size_t)((mode == 0) ? r0 : off + r0) * Nfull;
        size_t cr1 = (size_t)((mode == 0) ? r1 : off + r1) * Nfull;
        #pragma unroll
        for (int nt = 0; nt < NT; nt++){
            int col = n0 + wn + nt*8 + 2*lt;
            if (v0) *(float2*)(C + cr0 + col) = make_float2(acc[mt][nt][0], acc[mt][nt][1]);
            if (v1) *(float2*)(C + cr1 + col) = make_float2(acc[mt][nt][2], acc[mt][nt][3]);
        }
    }
}

// ---------------- fused gate_up + silu GEMM (BM=64, two 64-wide halves) ----------------
// g = A@B[:, n0..n0+64), u = A@B[:, n0+Nfull/2 ..), writes silu(g)*u (pitch halfN).
// mode 0: dense rows. mode 1: grouped, gather via g_perm.
__global__ void __launch_bounds__(256, 2) mma_gemm_silu(
    const float* __restrict__ A, const float* __restrict__ B, float* __restrict__ Cact,
    int Kd, int Nfull, long long BexpStride, int mode)
{
    const int halfN = Nfull >> 1;
    extern __shared__ __align__(16) uint32_t smemu[];
    uint32_t* As = smemu;                       // [2][A_SZ]
    uint32_t* Bs = smemu + 2*A_SZ;              // [2][2*BH_SZ] (g half, u half)
    const float** rowptr = (const float**)(smemu + 2*A_SZ + 4*BH_SZ);

    int tid = threadIdx.x, wid = tid >> 5, lane = tid & 31;
    int n0 = blockIdx.x * BNH, m0 = blockIdx.y * 64;
    int cnt = 1 << 30, off = 0;
    const float* Bm = B;
    if (mode){
        int e = blockIdx.z;
        cnt = g_cnt[e]; if (cnt > CAP) cnt = CAP;
        if (m0 >= cnt) return;
        off = g_off[e];
        Bm = B + (size_t)e * (size_t)BexpStride;
    }
    if (tid < 64){
        int m = m0 + tid;
        const float* src;
        if (mode == 0)      src = A + (size_t)m * Kd;
        else if (m >= cnt)  src = A;
        else                src = A + (size_t)(g_perm[off + m] / KTOP) * Kd;
        rowptr[tid] = src;
    }
    __syncthreads();

    int arow = tid >> 2, aoff = (tid & 3) * 8;
    int k2l = tid >> 4, colg = tid & 15;
    int cb = colg * 4;
    const float* aptr = rowptr[arow] + aoff;
    const float* bg0 = Bm + (size_t)(2*k2l) * Nfull + n0 + cb;
    const float* bg1 = bg0 + Nfull;

    const int NK = Kd / BKT;
    float4 pa0, pa1, pg0, pg1, pu0, pu1;

    auto ldg = [&](int kt){
        size_t kc = (size_t)kt * BKT;
        pa0 = *(const float4*)(aptr + kc);
        pa1 = *(const float4*)(aptr + kc + 4);
        size_t bo = kc * Nfull;
        pg0 = *(const float4*)(bg0 + bo);
        pg1 = *(const float4*)(bg1 + bo);
        pu0 = *(const float4*)(bg0 + bo + halfN);
        pu1 = *(const float4*)(bg1 + bo + halfN);
    };

    auto sts = [&](int s){
        uint32_t o[8];
        split_pair(pa0.x, pa0.y, o[0], o[1]);
        split_pair(pa0.z, pa0.w, o[2], o[3]);
        split_pair(pa1.x, pa1.y, o[4], o[5]);
        split_pair(pa1.z, pa1.w, o[6], o[7]);
        uint32_t* ad = As + s*A_SZ + arow*APW + aoff;
        *(uint4*)ad       = *(uint4*)&o[0];
        *(uint4*)(ad + 4) = *(uint4*)&o[4];
        uint32_t b[8];
        split_pair(pg0.x, pg1.x, b[0], b[1]);
        split_pair(pg0.y, pg1.y, b[2], b[3]);
        split_pair(pg0.z, pg1.z, b[4], b[5]);
        split_pair(pg0.w, pg1.w, b[6], b[7]);
        uint32_t* bd = Bs + s*2*BH_SZ + k2l*BPWH + 2*cb;
        *(uint4*)bd       = *(uint4*)&b[0];
        *(uint4*)(bd + 4) = *(uint4*)&b[4];
        split_pair(pu0.x, pu1.x, b[0], b[1]);
        split_pair(pu0.y, pu1.y, b[2], b[3]);
        split_pair(pu0.z, pu1.z, b[4], b[5]);
        split_pair(pu0.w, pu1.w, b[6], b[7]);
        bd += BH_SZ;
        *(uint4*)bd       = *(uint4*)&b[0];
        *(uint4*)(bd + 4) = *(uint4*)&b[4];
    };

    float acc[2][2][2][4];   // [m][half][nt][v]
    #pragma unroll
    for (int i = 0; i < 2; i++)
        #pragma unroll
        for (int hh = 0; hh < 2; hh++)
            #pragma unroll
            for (int j = 0; j < 2; j++)
                #pragma unroll
                for (int v = 0; v < 4; v++) acc[i][hh][j][v] = 0.f;

    int wm = (wid >> 2) * 32, wn = (wid & 3) * 16;
    int lg = lane >> 2, lt = lane & 3;

    ldg(0);
    for (int kt = 0; kt < NK; kt++){
        int s = kt & 1;
        sts(s);
        __syncthreads();
        if (kt + 1 < NK) ldg(kt + 1);

        const uint32_t* as = As + s*A_SZ;
        const uint32_t* bs = Bs + s*2*BH_SZ;
        #pragma unroll
        for (int ks = 0; ks < 2; ks++){
            int k2o = ks * 8;
            uint32_t ah[2][4], al[2][4], bh[2][2][2], bl[2][2][2];
            #pragma unroll
            for (int mt = 0; mt < 2; mt++){
                int row = wm + mt*16 + lg;
                uint2 v0 = *(const uint2*)(as + row*APW     + 2*(k2o+lt));
                uint2 v1 = *(const uint2*)(as + (row+8)*APW + 2*(k2o+lt));
                uint2 v2 = *(const uint2*)(as + row*APW     + 2*(k2o+4+lt));
                uint2 v3 = *(const uint2*)(as + (row+8)*APW + 2*(k2o+4+lt));
                ah[mt][0]=v0.x; al[mt][0]=v0.y;
                ah[mt][1]=v1.x; al[mt][1]=v1.y;
                ah[mt][2]=v2.x; al[mt][2]=v2.y;
                ah[mt][3]=v3.x; al[mt][3]=v3.y;
            }
            #pragma unroll
            for (int hh = 0; hh < 2; hh++)
                #pragma unroll
                for (int nt = 0; nt < 2; nt++){
                    int n = wn + nt*8 + lg;
                    const uint32_t* bb = bs + hh*BH_SZ;
                    uint2 w0 = *(const uint2*)(bb + (k2o+lt)*BPWH   + 2*n);
                    uint2 w1 = *(const uint2*)(bb + (k2o+4+lt)*BPWH + 2*n);
                    bh[hh][nt][0]=w0.x; bl[hh][nt][0]=w0.y;
                    bh[hh][nt][1]=w1.x; bl[hh][nt][1]=w1.y;
                }
            #pragma unroll
            for (int mt = 0; mt < 2; mt++)
                #pragma unroll
                for (int hh = 0; hh < 2; hh++)
                    #pragma unroll
                    for (int nt = 0; nt < 2; nt++){
                        mma_bf16(acc[mt][hh][nt], ah[mt], bh[hh][nt]);
                        mma_bf16(acc[mt][hh][nt], ah[mt], bl[hh][nt]);
                        mma_bf16(acc[mt][hh][nt], al[mt], bh[hh][nt]);
                    }
        }
        __syncthreads();
    }

    #pragma unroll
    for (int mt = 0; mt < 2; mt++){
        int r0 = m0 + wm + mt*16 + lg;
        int r1 = r0 + 8;
        bool v0 = (mode == 0) || (r0 < cnt);
        bool v1 = (mode == 0) || (r1 < cnt);
        size_t cr0 = (size_t)((mode == 0) ? r0 : off + r0) * halfN;
        size_t cr1 = (size_t)((mode == 0) ? r1 : off + r1) * halfN;
        #pragma unroll
        for (int nt = 0; nt < 2; nt++){
            int col = n0 + wn + nt*8 + 2*lt;
            if (v0){
                float2 o = make_float2(silu_mul(acc[mt][0][nt][0], acc[mt][1][nt][0]),
                                       silu_mul(acc[mt][0][nt][1], acc[mt][1][nt][1]));
                *(float2*)(Cact + cr0 + col) = o;
            }
            if (v1){
                float2 o = make_float2(silu_mul(acc[mt][0][nt][2], acc[mt][1][nt][2]),
                                       silu_mul(acc[mt][0][nt][3], acc[mt][1][nt][3]));
                *(float2*)(Cact + cr1 + col) = o;
            }
        }
    }
}

// ---------------- router: 8 tokens per block ----------------
__global__ __launch_bounds__(256) void router_topk(
    const float* __restrict__ x, const float* __restrict__ gw, const float* __restrict__ bias)
{
    __shared__ float xs[8][H];
    __shared__ float part[4][8][64];
    __shared__ float sc[8][64], sbb[8][64];
    int t0 = blockIdx.x * 8;
    for (int i = threadIdx.x; i < 8 * (H/4); i += 256){
        int tk = i / (H/4), j = i % (H/4);
        ((float4*)xs[tk])[j] = ((const float4*)(x + (size_t)(t0 + tk) * H))[j];
    }
    __syncthreads();
    int c = threadIdx.x >> 6, e = threadIdx.x & 63;
    float acc[8];
    #pragma unroll
    for (int tk = 0; tk < 8; tk++) acc[tk] = 0.f;
    const float* w = gw + (size_t)c * 256 * 64 + e;
    for (int h = 0; h < 256; h++){
        float wv = w[(size_t)h * 64];
        float* xcol = &xs[0][c * 256 + h];
        #pragma unroll
        for (int tk = 0; tk < 8; tk++) acc[tk] += xcol[tk * H] * wv;
    }
    #pragma unroll
    for (int tk = 0; tk < 8; tk++) part[c][tk][e] = acc[tk];
    __syncthreads();
    for (int i = threadIdx.x; i < 512; i += 256){
        int tk = i >> 6, ee = i & 63;
        float l = part[0][tk][ee] + part[1][tk][ee] + part[2][tk][ee] + part[3][tk][ee];
        float s = 1.f / (1.f + expf(-l));
        sc[tk][ee] = s; sbb[tk][ee] = s + bias[ee];
    }
    __syncthreads();
    if (threadIdx.x < 8){
        int tk = threadIdx.x;
        int t = t0 + tk;
        float gs[NGRP];
        #pragma unroll
        for (int g = 0; g < NGRP; g++){
            float m1 = -1e30f, m2 = -1e30f;
            #pragma unroll
            for (int j = 0; j < 8; j++){
                float v = sbb[tk][g * 8 + j];
                if (v > m1){ m2 = m1; m1 = v; } else if (v > m2){ m2 = v; }
            }
            gs[g] = m1 + m2;
        }
        unsigned gsel = 0;
        #pragma unroll
        for (int it = 0; it < TKG; it++){
            float best = -1e30f; int bi = 0;
            for (int g = 0; g < NGRP; g++)
                if (!((gsel >> g) & 1) && gs[g] > best){ best = gs[g]; bi = g; }
            gsel |= 1u << bi;
        }
        unsigned long long used = 0; float wsum = 0.f;
        float wk[KTOP]; int ek[KTOP];
        #pragma unroll
        for (int it = 0; it < KTOP; it++){
            float best = -1e30f; int bi = 0;
            for (int ee = 0; ee < 64; ee++){
                if (((gsel >> (ee >> 3)) & 1) && !((used >> ee) & 1) && sbb[tk][ee] > best){
                    best = sbb[tk][ee]; bi = ee;
                }
            }
            used |= 1ull << bi;
            ek[it] = bi; wk[it] = sc[tk][bi]; wsum += sc[tk][bi];
        }
        float inv = 1.f / wsum;
        #pragma unroll
        for (int k = 0; k < KTOP; k++){
            g_eidx[t * KTOP + k] = ek[k];
            g_w[t * KTOP + k] = wk[k] * inv;
        }
    }
}

// ---------------- fused dispatch ----------------
__global__ __launch_bounds__(1024) void dispatch_k()
{
    int tid = threadIdx.x;
    if (tid < E) g_cnt[tid] = 0;
    __syncthreads();
    for (int a = tid; a < A_TOT; a += 1024)
        g_slot[a] = atomicAdd(&g_cnt[g_eidx[a]], 1);
    __syncthreads();
    if (tid == 0){
        int s = 0;
        for (int e = 0; e < E; e++){
            g_off[e] = s;
            int c = g_cnt[e];
            s += (c > CAP) ? CAP : c;
        }
        g_off[E] = s;
    }
    __syncthreads();
    for (int a = tid; a < A_TOT; a += 1024){
        int e = g_eidx[a], sl = g_slot[a];
        if (sl < CAP){ int r = g_off[e] + sl; g_perm[r] = a; g_rowpos[a] = r; }
        else g_rowpos[a] = -1;
    }
}

// ---------------- combine ----------------
__global__ __launch_bounds__(256) void combine_k(float* __restrict__ out)
{
    int t = blockIdx.x;
    int h0 = threadIdx.x * 4;
    float4 acc = *(float4*)&out[(size_t)t * H + h0];
    #pragma unroll
    for (int k = 0; k < KTOP; k++){
        int a = t * KTOP + k;
        int r = g_rowpos[a];
        if (r >= 0){
            float w = 2.5f * g_w[a];
            float4 y = *(const float4*)&g_y[(size_t)r * H + h0];
            acc.x += w * y.x; acc.y += w * y.y; acc.z += w * y.z; acc.w += w * y.w;
        }
    }
    *(float4*)&out[(size_t)t * H + h0] = acc;
}

// ---------------- launch ----------------
extern "C" void kernel_launch(void* const* d_in, const int* in_sizes, int n_in,
                              void* d_out, int out_size)
{
    const float* x      = (const float*)d_in[0];
    const float* gate_w = (const float*)d_in[1];
    const float* e_bias = (const float*)d_in[2];
    const float* w_gu   = (const float*)d_in[3];
    const float* w_dn   = (const float*)d_in[4];
    const float* ws_gu  = (const float*)d_in[5];
    const float* ws_dn  = (const float*)d_in[6];
    float* out = (float*)d_out;

    float *p_actS, *p_act, *p_y;
    cudaGetSymbolAddress((void**)&p_actS, g_actS);
    cudaGetSymbolAddress((void**)&p_act,  g_act);
    cudaGetSymbolAddress((void**)&p_y,    g_y);

    const int SMEM_DN128 = (2*A_SZ + 2*(16*(2*128+8)))*4 + 64*8;
    const int SMEM_DN64  = (2*A_SZ + 2*(16*(2*64+8)))*4  + 64*8;
    const int SMEM_GU    = (2*A_SZ + 4*BH_SZ)*4 + 64*8;
    cudaFuncSetAttribute(mma_gemm<128>, cudaFuncAttributeMaxDynamicSharedMemorySize, SMEM_DN128);
    cudaFuncSetAttribute(mma_gemm<64>,  cudaFuncAttributeMaxDynamicSharedMemorySize, SMEM_DN64);
    cudaFuncSetAttribute(mma_gemm_silu, cudaFuncAttributeMaxDynamicSharedMemorySize, SMEM_GU);

    // router + dispatch
    router_topk<<<T/8, 256>>>(x, gate_w, e_bias);
    dispatch_k<<<1, 1024>>>();

    // shared experts: fused gate_up+silu -> actS, then down -> out
    mma_gemm_silu<<<dim3(NSH_HALF / BNH, T / 64, 1), 256, SMEM_GU>>>(
        x, ws_gu, p_actS, H, NSH_2, 0, 0);
    mma_gemm<64><<<dim3(H / 64, T / 64, 1), 256, SMEM_DN64>>>(
        p_actS, ws_dn, out, NSH_HALF, H, 0, 0);

    // routed experts: fused gate_up+silu (gathered) -> act, down -> y
    mma_gemm_silu<<<dim3(ISZ / BNH, CAP / 64, E), 256, SMEM_GU>>>(
        x, w_gu, p_act, H, TWO_I, (long long)H * TWO_I, 1);
    mma_gemm<128><<<dim3(H / 128, CAP / 64, E), 256, SMEM_DN128>>>(
        p_act, w_dn, p_y, ISZ, H, (long long)ISZ * H, 2);

    // combine
    combine_k<<<T, 256>>>(out);
}

// round 11
// speedup vs baseline: 2.8087x; 1.2748x over previous
#include <cuda_runtime.h>
#include <cuda_bf16.h>
#include <cstdint>
#include <math.h>

#define T 1024
#define H 1024
#define E 64
#define ISZ 512
#define TWO_I 1024
#define KTOP 6
#define NGRP 8
#define TKG 3
#define CAP 256
#define A_TOT (T*KTOP)
#define NSH_HALF 1024
#define NSH_2 2048

#define BKT 32
// A smem: two scalar bf16 planes (hi, lo), row pitch 40 bf16 = 20 words = 80B
#define PKW 20
#define A_PL 1280            // words per plane (64 rows * 20)
#define A_STG 2560           // words per stage (hi+lo)
#define A_STG_B 10240        // bytes per stage
#define A_PL_B 5120          // bytes per plane

// ---------------- scratch ----------------
__device__ float g_w[A_TOT];
__device__ int   g_eidx[A_TOT];
__device__ int   g_cnt[E];
__device__ int   g_off[E+1];
__device__ int   g_slot[A_TOT];
__device__ int   g_perm[A_TOT];
__device__ int   g_rowpos[A_TOT];
__device__ float g_actS[T*NSH_HALF];
__device__ float g_act[A_TOT*ISZ];
__device__ float g_y[A_TOT*H];

// ---------------- helpers ----------------
__device__ __forceinline__ uint32_t smem_u32(const void* p){
    uint32_t a;
    asm("{ .reg .u64 t; cvta.to.shared.u64 t, %1; cvt.u32.u64 %0, t; }" : "=r"(a) : "l"(p));
    return a;
}

__device__ __forceinline__ void mma_bf16(float* c, const uint32_t* a, const uint32_t* b){
    asm volatile(
        "mma.sync.aligned.m16n8k16.row.col.f32.bf16.bf16.f32 "
        "{%0,%1,%2,%3}, {%4,%5,%6,%7}, {%8,%9}, {%0,%1,%2,%3};"
        : "+f"(c[0]), "+f"(c[1]), "+f"(c[2]), "+f"(c[3])
        : "r"(a[0]), "r"(a[1]), "r"(a[2]), "r"(a[3]), "r"(b[0]), "r"(b[1]));
}

__device__ __forceinline__ void ldsm_x4(uint32_t& r0, uint32_t& r1, uint32_t& r2, uint32_t& r3, uint32_t addr){
    asm volatile("ldmatrix.sync.aligned.m8n8.x4.shared.b16 {%0,%1,%2,%3}, [%4];"
                 : "=r"(r0), "=r"(r1), "=r"(r2), "=r"(r3) : "r"(addr));
}
__device__ __forceinline__ void ldsm_x4_t(uint32_t& r0, uint32_t& r1, uint32_t& r2, uint32_t& r3, uint32_t addr){
    asm volatile("ldmatrix.sync.aligned.m8n8.x4.trans.shared.b16 {%0,%1,%2,%3}, [%4];"
                 : "=r"(r0), "=r"(r1), "=r"(r2), "=r"(r3) : "r"(addr));
}

// hi = truncate-to-bf16 of (x0,x1) packed; lo = rn-bf16 of remainders packed.
__device__ __forceinline__ void split_pair(float x0, float x1, uint32_t& h, uint32_t& l){
    uint32_t u0 = __float_as_uint(x0), u1 = __float_as_uint(x1);
    h = __byte_perm(u0, u1, 0x7632);
    float f0 = __uint_as_float(u0 & 0xFFFF0000u);
    float f1 = __uint_as_float(u1 & 0xFFFF0000u);
    __nv_bfloat162 lv = __floats2bfloat162_rn(x0 - f0, x1 - f1);
    l = *reinterpret_cast<uint32_t*>(&lv);
}

__device__ __forceinline__ float silu_mul(float g, float u){
    return (g / (1.f + expf(-g))) * u;
}

// ---------------- down-proj bf16x3 GEMM (BM=64, templated BN) ----------------
// mode 0: dense rows. mode 2: grouped rows = off[e]+m.
template<int BNv>
__global__ void __launch_bounds__(256, 2) mma_gemm(
    const float* __restrict__ A, const float* __restrict__ B, float* __restrict__ C,
    int Kd, int Nfull, long long BexpStride, int mode)
{
    constexpr int PNW  = (BNv + 8) / 2;     // words per B row per plane
    constexpr int B_PL = 32 * PNW;          // words per B plane
    constexpr int B_STG = 2 * B_PL;         // words per B stage (hi+lo)
    constexpr int CPB  = BNv / 16;          // B cols per loader thread
    constexpr int NF   = BNv / 32;          // n8 fragments per warp
    constexpr int NG   = NF / 2;            // ldsm n16 groups per warp
    extern __shared__ __align__(16) uint32_t smemu[];
    uint32_t* As = smemu;                   // [2][A_STG]
    uint32_t* Bs = smemu + 2*A_STG;         // [2][B_STG]
    const float** rowptr = (const float**)(smemu + 2*A_STG + 2*B_STG);

    int tid = threadIdx.x, wid = tid >> 5, lane = tid & 31;
    int n0 = blockIdx.x * BNv, m0 = blockIdx.y * 64;
    int cnt = 1 << 30, off = 0;
    const float* Bm = B;
    if (mode){
        int e = blockIdx.z;
        cnt = g_cnt[e]; if (cnt > CAP) cnt = CAP;
        if (m0 >= cnt) return;
        off = g_off[e];
        Bm = B + (size_t)e * (size_t)BexpStride;
    }
    if (tid < 64){
        int m = m0 + tid;
        const float* src;
        if (mode == 0)      src = A + (size_t)m * Kd;
        else if (m >= cnt)  src = A;
        else                src = A + (size_t)(off + m) * Kd;
        rowptr[tid] = src;
    }
    __syncthreads();

    // loader geometry
    int arow = tid >> 2, aoff = (tid & 3) * 8;
    int k2l = tid >> 4, colg = tid & 15;
    int cb = colg * CPB;
    const float* aptr = rowptr[arow] + aoff;
    const float* bptr0 = Bm + (size_t)(2*k2l) * Nfull + n0 + cb;
    const float* bptr1 = bptr0 + Nfull;

    const int NK = Kd / BKT;
    float4 pa0, pa1;
    float4 pb[CPB/4], qb[CPB/4];

    auto ldg = [&](int kt){
        size_t kc = (size_t)kt * BKT;
        pa0 = *(const float4*)(aptr + kc);
        pa1 = *(const float4*)(aptr + kc + 4);
        size_t bo = kc * Nfull;
        #pragma unroll
        for (int j = 0; j < CPB/4; j++){
            pb[j] = *(const float4*)(bptr0 + bo + 4*j);
            qb[j] = *(const float4*)(bptr1 + bo + 4*j);
        }
    };

    auto sts = [&](int s){
        // A: split into hi/lo planes
        uint32_t h[4], l[4];
        split_pair(pa0.x, pa0.y, h[0], l[0]);
        split_pair(pa0.z, pa0.w, h[1], l[1]);
        split_pair(pa1.x, pa1.y, h[2], l[2]);
        split_pair(pa1.z, pa1.w, h[3], l[3]);
        uint32_t* ad = As + s*A_STG + arow*PKW + (aoff >> 1);
        *(uint4*)ad          = make_uint4(h[0], h[1], h[2], h[3]);
        *(uint4*)(ad + A_PL) = make_uint4(l[0], l[1], l[2], l[3]);
        // B rows 2k2l, 2k2l+1
        uint32_t* bd = Bs + s*B_STG + (2*k2l)*PNW + (cb >> 1);
        uint32_t hb[CPB/2], lb[CPB/2];
        #pragma unroll
        for (int j = 0; j < CPB/4; j++){
            split_pair(pb[j].x, pb[j].y, hb[2*j],   lb[2*j]);
            split_pair(pb[j].z, pb[j].w, hb[2*j+1], lb[2*j+1]);
        }
        if (CPB == 8){
            *(uint4*)bd          = *(uint4*)hb;
            *(uint4*)(bd + B_PL) = *(uint4*)lb;
        } else {
            *(uint2*)bd          = *(uint2*)hb;
            *(uint2*)(bd + B_PL) = *(uint2*)lb;
        }
        #pragma unroll
        for (int j = 0; j < CPB/4; j++){
            split_pair(qb[j].x, qb[j].y, hb[2*j],   lb[2*j]);
            split_pair(qb[j].z, qb[j].w, hb[2*j+1], lb[2*j+1]);
        }
        bd += PNW;
        if (CPB == 8){
            *(uint4*)bd          = *(uint4*)hb;
            *(uint4*)(bd + B_PL) = *(uint4*)lb;
        } else {
            *(uint2*)bd          = *(uint2*)hb;
            *(uint2*)(bd + B_PL) = *(uint2*)lb;
        }
    };

    float acc[2][NF][4];
    #pragma unroll
    for (int i = 0; i < 2; i++)
        #pragma unroll
        for (int j = 0; j < NF; j++)
            #pragma unroll
            for (int v = 0; v < 4; v++) acc[i][j][v] = 0.f;

    int wm = (wid >> 2) * 32, wn = (wid & 3) * (NF*8);
    int lg = lane >> 2, lt = lane & 3;

    // ldmatrix lane addressing (same formula for A rows / B k-rows)
    int lr = (lane & 7) + ((lane >> 3) & 1) * 8;
    int lk = (lane >> 4) * 8;
    uint32_t As_u = smem_u32(As), Bs_u = smem_u32(Bs);
    uint32_t aad[2];
    aad[0] = As_u + (uint32_t)(wm + lr) * 80u + (uint32_t)lk * 2u;
    aad[1] = aad[0] + 16u * 80u;
    uint32_t bad[NG];
    #pragma unroll
    for (int g = 0; g < NG; g++)
        bad[g] = Bs_u + (uint32_t)lr * (PNW*4u) + (uint32_t)(wn + g*16 + lk) * 2u;

    ldg(0);
    for (int kt = 0; kt < NK; kt++){
        int s = kt & 1;
        sts(s);
        __syncthreads();
        if (kt + 1 < NK) ldg(kt + 1);

        uint32_t aS = s ? (uint32_t)A_STG_B : 0u;
        uint32_t bS = s ? (uint32_t)(B_STG*4) : 0u;
        #pragma unroll
        for (int ks = 0; ks < 2; ks++){
            uint32_t ah[2][4], al[2][4], bh[NF][2], bl[NF][2];
            #pragma unroll
            for (int mt = 0; mt < 2; mt++){
                uint32_t a0 = aad[mt] + aS + ks*32u;
                ldsm_x4(ah[mt][0], ah[mt][1], ah[mt][2], ah[mt][3], a0);
                ldsm_x4(al[mt][0], al[mt][1], al[mt][2], al[mt][3], a0 + A_PL_B);
            }
            #pragma unroll
            for (int g = 0; g < NG; g++){
                uint32_t b0 = bad[g] + bS + (uint32_t)(ks*16*PNW*4);
                ldsm_x4_t(bh[2*g][0], bh[2*g][1], bh[2*g+1][0], bh[2*g+1][1], b0);
                ldsm_x4_t(bl[2*g][0], bl[2*g][1], bl[2*g+1][0], bl[2*g+1][1], b0 + B_PL*4);
            }
            #pragma unroll
            for (int mt = 0; mt < 2; mt++)
                #pragma unroll
                for (int nt = 0; nt < NF; nt++){
                    mma_bf16(acc[mt][nt], ah[mt], bh[nt]);
                    mma_bf16(acc[mt][nt], ah[mt], bl[nt]);
                    mma_bf16(acc[mt][nt], al[mt], bh[nt]);
                }
        }
        __syncthreads();
    }

    #pragma unroll
    for (int mt = 0; mt < 2; mt++){
        int r0 = m0 + wm + mt*16 + lg;
        int r1 = r0 + 8;
        bool v0 = (mode == 0) || (r0 < cnt);
        bool v1 = (mode == 0) || (r1 < cnt);
        size_t cr0 = (size_t)((mode == 0) ? r0 : off + r0) * Nfull;
        size_t cr1 = (size_t)((mode == 0) ? r1 : off + r1) * Nfull;
        #pragma unroll
        for (int nt = 0; nt < NF; nt++){
            int col = n0 + wn + nt*8 + 2*lt;
            if (v0) *(float2*)(C + cr0 + col) = make_float2(acc[mt][nt][0], acc[mt][nt][1]);
            if (v1) *(float2*)(C + cr1 + col) = make_float2(acc[mt][nt][2], acc[mt][nt][3]);
        }
    }
}

// ---------------- fused gate_up + silu GEMM (BM=64, two 64-wide halves) ----------------
#define GPNW 36
#define GB_PL (32*GPNW)         // 1152 words per plane
#define GB_STG (4*GB_PL)        // hi_g, lo_g, hi_u, lo_u
__global__ void __launch_bounds__(256, 2) mma_gemm_silu(
    const float* __restrict__ A, const float* __restrict__ B, float* __restrict__ Cact,
    int Kd, int Nfull, long long BexpStride, int mode)
{
    const int halfN = Nfull >> 1;
    extern __shared__ __align__(16) uint32_t smemu[];
    uint32_t* As = smemu;                   // [2][A_STG]
    uint32_t* Bs = smemu + 2*A_STG;         // [2][GB_STG]
    const float** rowptr = (const float**)(smemu + 2*A_STG + 2*GB_STG);

    int tid = threadIdx.x, wid = tid >> 5, lane = tid & 31;
    int n0 = blockIdx.x * 64, m0 = blockIdx.y * 64;
    int cnt = 1 << 30, off = 0;
    const float* Bm = B;
    if (mode){
        int e = blockIdx.z;
        cnt = g_cnt[e]; if (cnt > CAP) cnt = CAP;
        if (m0 >= cnt) return;
        off = g_off[e];
        Bm = B + (size_t)e * (size_t)BexpStride;
    }
    if (tid < 64){
        int m = m0 + tid;
        const float* src;
        if (mode == 0)      src = A + (size_t)m * Kd;
        else if (m >= cnt)  src = A;
        else                src = A + (size_t)(g_perm[off + m] / KTOP) * Kd;
        rowptr[tid] = src;
    }
    __syncthreads();

    int arow = tid >> 2, aoff = (tid & 3) * 8;
    int k2l = tid >> 4, colg = tid & 15;
    int cb = colg * 4;
    const float* aptr = rowptr[arow] + aoff;
    const float* bg0 = Bm + (size_t)(2*k2l) * Nfull + n0 + cb;
    const float* bg1 = bg0 + Nfull;

    const int NK = Kd / BKT;
    float4 pa0, pa1, pg0, pg1, pu0, pu1;

    auto ldg = [&](int kt){
        size_t kc = (size_t)kt * BKT;
        pa0 = *(const float4*)(aptr + kc);
        pa1 = *(const float4*)(aptr + kc + 4);
        size_t bo = kc * Nfull;
        pg0 = *(const float4*)(bg0 + bo);
        pg1 = *(const float4*)(bg1 + bo);
        pu0 = *(const float4*)(bg0 + bo + halfN);
        pu1 = *(const float4*)(bg1 + bo + halfN);
    };

    auto sts = [&](int s){
        uint32_t h[4], l[4];
        split_pair(pa0.x, pa0.y, h[0], l[0]);
        split_pair(pa0.z, pa0.w, h[1], l[1]);
        split_pair(pa1.x, pa1.y, h[2], l[2]);
        split_pair(pa1.z, pa1.w, h[3], l[3]);
        uint32_t* ad = As + s*A_STG + arow*PKW + (aoff >> 1);
        *(uint4*)ad          = make_uint4(h[0], h[1], h[2], h[3]);
        *(uint4*)(ad + A_PL) = make_uint4(l[0], l[1], l[2], l[3]);

        uint32_t h0, h1, l0, l1;
        uint32_t* bd = Bs + s*GB_STG + (2*k2l)*GPNW + (cb >> 1);
        split_pair(pg0.x, pg0.y, h0, l0); split_pair(pg0.z, pg0.w, h1, l1);
        *(uint2*)bd           = make_uint2(h0, h1);
        *(uint2*)(bd + GB_PL) = make_uint2(l0, l1);
        split_pair(pg1.x, pg1.y, h0, l0); split_pair(pg1.z, pg1.w, h1, l1);
        *(uint2*)(bd + GPNW)          = make_uint2(h0, h1);
        *(uint2*)(bd + GPNW + GB_PL)  = make_uint2(l0, l1);
        bd += 2*GB_PL;
        split_pair(pu0.x, pu0.y, h0, l0); split_pair(pu0.z, pu0.w, h1, l1);
        *(uint2*)bd           = make_uint2(h0, h1);
        *(uint2*)(bd + GB_PL) = make_uint2(l0, l1);
        split_pair(pu1.x, pu1.y, h0, l0); split_pair(pu1.z, pu1.w, h1, l1);
        *(uint2*)(bd + GPNW)          = make_uint2(h0, h1);
        *(uint2*)(bd + GPNW + GB_PL)  = make_uint2(l0, l1);
    };

    float acc[2][2][2][4];   // [m][half][nt][v]
    #pragma unroll
    for (int i = 0; i < 2; i++)
        #pragma unroll
        for (int hh = 0; hh < 2; hh++)
            #pragma unroll
            for (int j = 0; j < 2; j++)
                #pragma unroll
                for (int v = 0; v < 4; v++) acc[i][hh][j][v] = 0.f;

    int wm = (wid >> 2) * 32, wn = (wid & 3) * 16;
    int lg = lane >> 2, lt = lane & 3;

    int lr = (lane & 7) + ((lane >> 3) & 1) * 8;
    int lk = (lane >> 4) * 8;
    uint32_t As_u = smem_u32(As), Bs_u = smem_u32(Bs);
    uint32_t aad[2];
    aad[0] = As_u + (uint32_t)(wm + lr) * 80u + (uint32_t)lk * 2u;
    aad[1] = aad[0] + 16u * 80u;
    uint32_t bad[2];
    #pragma unroll
    for (int hh = 0; hh < 2; hh++)
        bad[hh] = Bs_u + (uint32_t)(hh * 2 * GB_PL * 4) + (uint32_t)lr * (GPNW*4u) + (uint32_t)(wn + lk) * 2u;

    ldg(0);
    for (int kt = 0; kt < NK; kt++){
        int s = kt & 1;
        sts(s);
        __syncthreads();
        if (kt + 1 < NK) ldg(kt + 1);

        uint32_t aS = s ? (uint32_t)A_STG_B : 0u;
        uint32_t bS = s ? (uint32_t)(GB_STG*4) : 0u;
        #pragma unroll
        for (int ks = 0; ks < 2; ks++){
            uint32_t ah[2][4], al[2][4], bh[2][2][2], bl[2][2][2];
            #pragma unroll
            for (int mt = 0; mt < 2; mt++){
                uint32_t a0 = aad[mt] + aS + ks*32u;
                ldsm_x4(ah[mt][0], ah[mt][1], ah[mt][2], ah[mt][3], a0);
                ldsm_x4(al[mt][0], al[mt][1], al[mt][2], al[mt][3], a0 + A_PL_B);
            }
            #pragma unroll
            for (int hh = 0; hh < 2; hh++){
                uint32_t b0 = bad[hh] + bS + (uint32_t)(ks*16*GPNW*4);
                ldsm_x4_t(bh[hh][0][0], bh[hh][0][1], bh[hh][1][0], bh[hh][1][1], b0);
                ldsm_x4_t(bl[hh][0][0], bl[hh][0][1], bl[hh][1][0], bl[hh][1][1], b0 + GB_PL*4);
            }
            #pragma unroll
            for (int mt = 0; mt < 2; mt++)
                #pragma unroll
                for (int hh = 0; hh < 2; hh++)
                    #pragma unroll
                    for (int nt = 0; nt < 2; nt++){
                        mma_bf16(acc[mt][hh][nt], ah[mt], bh[hh][nt]);
                        mma_bf16(acc[mt][hh][nt], ah[mt], bl[hh][nt]);
                        mma_bf16(acc[mt][hh][nt], al[mt], bh[hh][nt]);
                    }
        }
        __syncthreads();
    }

    #pragma unroll
    for (int mt = 0; mt < 2; mt++){
        int r0 = m0 + wm + mt*16 + lg;
        int r1 = r0 + 8;
        bool v0 = (mode == 0) || (r0 < cnt);
        bool v1 = (mode == 0) || (r1 < cnt);
        size_t cr0 = (size_t)((mode == 0) ? r0 : off + r0) * halfN;
        size_t cr1 = (size_t)((mode == 0) ? r1 : off + r1) * halfN;
        #pragma unroll
        for (int nt = 0; nt < 2; nt++){
            int col = n0 + wn + nt*8 + 2*lt;
            if (v0){
                float2 o = make_float2(silu_mul(acc[mt][0][nt][0], acc[mt][1][nt][0]),
                                       silu_mul(acc[mt][0][nt][1], acc[mt][1][nt][1]));
                *(float2*)(Cact + cr0 + col) = o;
            }
            if (v1){
                float2 o = make_float2(silu_mul(acc[mt][0][nt][2], acc[mt][1][nt][2]),
                                       silu_mul(acc[mt][0][nt][3], acc[mt][1][nt][3]));
                *(float2*)(Cact + cr1 + col) = o;
            }
        }
    }
}

// ---------------- router: 8 tokens per block ----------------
__global__ __launch_bounds__(256) void router_topk(
    const float* __restrict__ x, const float* __restrict__ gw, const float* __restrict__ bias)
{
    __shared__ float xs[8][H];
    __shared__ float part[4][8][64];
    __shared__ float sc[8][64], sbb[8][64];
    int t0 = blockIdx.x * 8;
    for (int i = threadIdx.x; i < 8 * (H/4); i += 256){
        int tk = i / (H/4), j = i % (H/4);
        ((float4*)xs[tk])[j] = ((const float4*)(x + (size_t)(t0 + tk) * H))[j];
    }
    __syncthreads();
    int c = threadIdx.x >> 6, e = threadIdx.x & 63;
    float acc[8];
    #pragma unroll
    for (int tk = 0; tk < 8; tk++) acc[tk] = 0.f;
    const float* w = gw + (size_t)c * 256 * 64 + e;
    for (int h = 0; h < 256; h++){
        float wv = w[(size_t)h * 64];
        float* xcol = &xs[0][c * 256 + h];
        #pragma unroll
        for (int tk = 0; tk < 8; tk++) acc[tk] += xcol[tk * H] * wv;
    }
    #pragma unroll
    for (int tk = 0; tk < 8; tk++) part[c][tk][e] = acc[tk];
    __syncthreads();
    for (int i = threadIdx.x; i < 512; i += 256){
        int tk = i >> 6, ee = i & 63;
        float l = part[0][tk][ee] + part[1][tk][ee] + part[2][tk][ee] + part[3][tk][ee];
        float s = 1.f / (1.f + expf(-l));
        sc[tk][ee] = s; sbb[tk][ee] = s + bias[ee];
    }
    __syncthreads();
    if (threadIdx.x < 8){
        int tk = threadIdx.x;
        int t = t0 + tk;
        float gs[NGRP];
        #pragma unroll
        for (int g = 0; g < NGRP; g++){
            float m1 = -1e30f, m2 = -1e30f;
            #pragma unroll
            for (int j = 0; j < 8; j++){
                float v = sbb[tk][g * 8 + j];
                if (v > m1){ m2 = m1; m1 = v; } else if (v > m2){ m2 = v; }
            }
            gs[g] = m1 + m2;
        }
        unsigned gsel = 0;
        #pragma unroll
        for (int it = 0; it < TKG; it++){
            float best = -1e30f; int bi = 0;
            for (int g = 0; g < NGRP; g++)
                if (!((gsel >> g) & 1) && gs[g] > best){ best = gs[g]; bi = g; }
            gsel |= 1u << bi;
        }
        unsigned long long used = 0; float wsum = 0.f;
        float wk[KTOP]; int ek[KTOP];
        #pragma unroll
        for (int it = 0; it < KTOP; it++){
            float best = -1e30f; int bi = 0;
            for (int ee = 0; ee < 64; ee++){
                if (((gsel >> (ee >> 3)) & 1) && !((used >> ee) & 1) && sbb[tk][ee] > best){
                    best = sbb[tk][ee]; bi = ee;
                }
            }
            used |= 1ull << bi;
            ek[it] = bi; wk[it] = sc[tk][bi]; wsum += sc[tk][bi];
        }
        float inv = 1.f / wsum;
        #pragma unroll
        for (int k = 0; k < KTOP; k++){
            g_eidx[t * KTOP + k] = ek[k];
            g_w[t * KTOP + k] = wk[k] * inv;
        }
    }
}

// ---------------- fused dispatch ----------------
__global__ __launch_bounds__(1024) void dispatch_k()
{
    int tid = threadIdx.x;
    if (tid < E) g_cnt[tid] = 0;
    __syncthreads();
    for (int a = tid; a < A_TOT; a += 1024)
        g_slot[a] = atomicAdd(&g_cnt[g_eidx[a]], 1);
    __syncthreads();
    if (tid == 0){
        int s = 0;
        for (int e = 0; e < E; e++){
            g_off[e] = s;
            int c = g_cnt[e];
            s += (c > CAP) ? CAP : c;
        }
        g_off[E] = s;
    }
    __syncthreads();
    for (int a = tid; a < A_TOT; a += 1024){
        int e = g_eidx[a], sl = g_slot[a];
        if (sl < CAP){ int r = g_off[e] + sl; g_perm[r] = a; g_rowpos[a] = r; }
        else g_rowpos[a] = -1;
    }
}

// ---------------- combine ----------------
__global__ __launch_bounds__(256) void combine_k(float* __restrict__ out)
{
    int t = blockIdx.x;
    int h0 = threadIdx.x * 4;
    float4 acc = *(float4*)&out[(size_t)t * H + h0];
    #pragma unroll
    for (int k = 0; k < KTOP; k++){
        int a = t * KTOP + k;
        int r = g_rowpos[a];
        if (r >= 0){
            float w = 2.5f * g_w[a];
            float4 y = *(const float4*)&g_y[(size_t)r * H + h0];
            acc.x += w * y.x; acc.y += w * y.y; acc.z += w * y.z; acc.w += w * y.w;
        }
    }
    *(float4*)&out[(size_t)t * H + h0] = acc;
}

// ---------------- launch ----------------
extern "C" void kernel_launch(void* const* d_in, const int* in_sizes, int n_in,
                              void* d_out, int out_size)
{
    const float* x      = (const float*)d_in[0];
    const float* gate_w = (const float*)d_in[1];
    const float* e_bias = (const float*)d_in[2];
    const float* w_gu   = (const float*)d_in[3];
    const float* w_dn   = (const float*)d_in[4];
    const float* ws_gu  = (const float*)d_in[5];
    const float* ws_dn  = (const float*)d_in[6];
    float* out = (float*)d_out;

    float *p_actS, *p_act, *p_y;
    cudaGetSymbolAddress((void**)&p_actS, g_actS);
    cudaGetSymbolAddress((void**)&p_act,  g_act);
    cudaGetSymbolAddress((void**)&p_y,    g_y);

    const int SMEM_DN128 = (2*A_STG + 2*2*(32*68))*4 + 64*8;
    const int SMEM_DN64  = (2*A_STG + 2*2*(32*36))*4 + 64*8;
    const int SMEM_GU    = (2*A_STG + 2*GB_STG)*4 + 64*8;
    cudaFuncSetAttribute(mma_gemm<128>, cudaFuncAttributeMaxDynamicSharedMemorySize, SMEM_DN128);
    cudaFuncSetAttribute(mma_gemm<64>,  cudaFuncAttributeMaxDynamicSharedMemorySize, SMEM_DN64);
    cudaFuncSetAttribute(mma_gemm_silu, cudaFuncAttributeMaxDynamicSharedMemorySize, SMEM_GU);

    // router + dispatch
    router_topk<<<T/8, 256>>>(x, gate_w, e_bias);
    dispatch_k<<<1, 1024>>>();

    // shared experts: fused gate_up+silu -> actS, then down -> out
    mma_gemm_silu<<<dim3(NSH_HALF / 64, T / 64, 1), 256, SMEM_GU>>>(
        x, ws_gu, p_actS, H, NSH_2, 0, 0);
    mma_gemm<64><<<dim3(H / 64, T / 64, 1), 256, SMEM_DN64>>>(
        p_actS, ws_dn, out, NSH_HALF, H, 0, 0);

    // routed experts: fused gate_up+silu (gathered) -> act, down -> y
    mma_gemm_silu<<<dim3(ISZ / 64, CAP / 64, E), 256, SMEM_GU>>>(
        x, w_gu, p_act, H, TWO_I, (long long)H * TWO_I, 1);
    mma_gemm<128><<<dim3(H / 128, CAP / 64, E), 256, SMEM_DN128>>>(
        p_act, w_dn, p_y, ISZ, H, (long long)ISZ * H, 2);

    // combine
    combine_k<<<T, 256>>>(out);
}